// round 12
// baseline (speedup 1.0000x reference)
#include <cuda_runtime.h>
#include <cuda_bf16.h>
#include <mma.h>
#include <cstdint>

using namespace nvcuda;

#define NB 8
#define NT 4096
#define NA 64
#define DD 256
#define MTOK (NB*NT)
#define W3 (3*DD)
#define SPL 32
#define TSPL 128   // tokens per split

// ---------------- scratch (device globals; no allocations allowed) ----------
__device__ __nv_bfloat16 g_xb[MTOK*DD];              // x in bf16
__device__ __nv_bfloat16 g_Wfc2[DD*DD];              // W_fc2 bf16 [K,N]
__device__ __nv_bfloat16 g_Wqkvb[DD*W3];             // W_qkv bf16 [K, 3N]
__device__ __nv_bfloat16 g_Wfc1b[DD*DD];             // W_fc1 bf16 [K,N]
__device__ __nv_bfloat16 g_qasb[NA*DD];              // qa_s bf16 (scale folded)
__device__ __nv_bfloat16 g_kasb[NA*DD];              // ka_s bf16 (scale folded)
__device__ float        g_kaf[NA*DD];                // ka_s fp32 (for dbias)
__device__ __nv_bfloat16 g_qap[NA*DD];               // qa' = qa_s @ Wk^T, bf16
__device__ __nv_bfloat16 g_kat[NA*DD];               // Ka' [a,i] bf16
__device__ float        g_dbias[NA];                 // bq . ka_s
__device__ __nv_bfloat16 g_Wvfb[DD*DD];              // Wv @ Wfc1, bf16
__device__ float        g_Wvf2[DD*DD];               // (Wv@Wfc1)@Wfc2, fp32
__device__ float        g_bvf[DD];                   // bv@Wfc1 + bfc1
__device__ float        g_bvf2[DD];                  // bvf @ Wfc2
__device__ float        g_vap[NB*SPL*NA*DD];         // unnormalized split partials
__device__ float2       g_stats[NB*SPL*NA];          // (m_s, s_s) per split-row
__device__ __nv_bfloat16 g_va[NB*NA*DD];             // va2 bf16

// ---------------- cp.async helpers ------------------------------------------
__device__ __forceinline__ uint32_t smem_u32(const void* p) {
    uint32_t a;
    asm("{ .reg .u64 t; cvta.to.shared.u64 t, %1; cvt.u32.u64 %0, t; }" : "=r"(a) : "l"(p));
    return a;
}
#define CPA16(s, g)  asm volatile("cp.async.cg.shared.global [%0], [%1], 16;" :: "r"(s), "l"(g))
#define CPA_COMMIT() asm volatile("cp.async.commit_group;" ::: "memory")
#define CPA_WAIT(n)  asm volatile("cp.async.wait_group %0;" :: "n"(n) : "memory")

// ================= prep0: conv_inputs || agent_proj ==========================
__global__ void __launch_bounds__(512) prep0(const float* __restrict__ x,
                                             const float* __restrict__ Wfc2,
                                             const float* __restrict__ Wqkv,
                                             const float* __restrict__ Wfc1,
                                             const float* __restrict__ agent,
                                             const float* __restrict__ Wag,
                                             const float* __restrict__ bag) {
    if (blockIdx.x < 1024) {
        int tid = blockIdx.x * 512 + threadIdx.x;
        int stride = 1024 * 512;
        for (int i = tid; i < (MTOK*DD)/4; i += stride) {
            float4 v = *(const float4*)(x + i*4);
            __nv_bfloat16 t[4] = {__float2bfloat16(v.x), __float2bfloat16(v.y),
                                  __float2bfloat16(v.z), __float2bfloat16(v.w)};
            *(uint2*)(g_xb + i*4) = *(uint2*)t;
        }
        for (int i = tid; i < DD*DD; i += stride)
            g_Wfc2[i] = __float2bfloat16(Wfc2[i]);
        for (int i = tid; i < DD*W3; i += stride)
            g_Wqkvb[i] = __float2bfloat16(Wqkv[i]);
        for (int i = tid; i < DD*DD; i += stride)
            g_Wfc1b[i] = __float2bfloat16(Wfc1[i]);
    } else {
        __shared__ float arow[DD];
        int a = blockIdx.x - 1024;
        for (int i = threadIdx.x; i < DD; i += 512)
            arow[i] = agent[a*DD + i];
        __syncthreads();
        int o = threadIdx.x;  // 0..511
        float s = 0.f;
        #pragma unroll 8
        for (int d = 0; d < DD; d++)
            s += arow[d] * Wag[d*2*DD + o];
        s += bag[o];
        s *= 0.0625f;  // 256^-0.5
        if (o < DD) {
            g_qasb[a*DD + o] = __float2bfloat16(s);
        } else {
            g_kasb[a*DD + (o-DD)] = __float2bfloat16(s);
            g_kaf [a*DD + (o-DD)] = s;
        }
    }
}

// ---------------- device: proj_agents tile -----------------------------------
__device__ void dev_proj_agents(char* sm, int ix, int sel) {
    __nv_bfloat16 (*Aa)[64][40] = (__nv_bfloat16(*)[64][40]) sm;
    __nv_bfloat16 (*Ws)[64][40] = (__nv_bfloat16(*)[64][40])(sm + 10240);
    float (*epi)[16][16]        = (float(*)[16][16])        (sm + 20480);
    uint32_t sA = smem_u32(sm), sW = sA + 10240u;

    int col0 = ix * 64;
    const __nv_bfloat16* A  = sel ? g_kasb : g_qasb;
    const __nv_bfloat16* Bb = g_Wqkvb + (sel ? 0 : DD);
    __nv_bfloat16* C = sel ? g_kat : g_qap;
    int tid = threadIdx.x;
    int w = tid >> 5, lane = tid & 31;
    int wm = w >> 2, wn = w & 3;

    wmma::fragment<wmma::accumulator,16,16,16,float> acc[2];
    #pragma unroll
    for (int i = 0; i < 2; i++) wmma::fill_fragment(acc[i], 0.f);

    #define PA_STAGE(kc, bb) {                                                     \
        {   int ar = tid >> 2, ac = (tid & 3) * 8;                                 \
            CPA16(sA + (uint32_t)(bb)*5120u + (uint32_t)ar*80u + (uint32_t)ac*2u,  \
                  A + (size_t)ar*DD + (kc) + ac); }                                \
        {   int wr = tid >> 2, wc = (tid & 3) * 8;                                 \
            CPA16(sW + (uint32_t)(bb)*5120u + (uint32_t)wr*80u + (uint32_t)wc*2u,  \
                  Bb + (size_t)(col0 + wr)*W3 + (kc) + wc); }                      \
        CPA_COMMIT(); }

    PA_STAGE(0, 0);
    for (int s = 0; s < 8; s++) {
        CPA_WAIT(0);
        __syncthreads();
        if (s < 7) PA_STAGE((s+1)*32, (s+1)&1);
        int bb = s & 1;
        #pragma unroll
        for (int kk = 0; kk < 2; kk++) {
            wmma::fragment<wmma::matrix_a,16,16,16,__nv_bfloat16,wmma::row_major> af[2];
            wmma::fragment<wmma::matrix_b,16,16,16,__nv_bfloat16,wmma::col_major> bf;
            #pragma unroll
            for (int i = 0; i < 2; i++)
                wmma::load_matrix_sync(af[i], &Aa[bb][wm*32 + i*16][kk*16], 40);
            wmma::load_matrix_sync(bf, &Ws[bb][wn*16][kk*16], 40);
            #pragma unroll
            for (int i = 0; i < 2; i++)
                wmma::mma_sync(acc[i], af[i], bf, acc[i]);
        }
    }
    #undef PA_STAGE

    #pragma unroll
    for (int i = 0; i < 2; i++) {
        wmma::store_matrix_sync(&epi[w][0][0], acc[i], 16, wmma::mem_row_major);
        __syncwarp();
        if (lane < 16) {
            int a = wm*32 + i*16 + lane;
            __nv_bfloat16 t8[8];
            #pragma unroll
            for (int g = 0; g < 2; g++) {
                #pragma unroll
                for (int e = 0; e < 8; e++)
                    t8[e] = __float2bfloat16(epi[w][lane][g*8+e]);
                *(uint4*)(C + (size_t)a*DD + col0 + wn*16 + g*8) = *(uint4*)t8;
            }
        }
        __syncwarp();
    }
}

// ---------------- device: 64x64 weight GEMM tile -----------------------------
__device__ void dev_w64(char* sm, int bx, int by, int sel) {
    __nv_bfloat16 (*As)[64][72] = (__nv_bfloat16(*)[64][72]) sm;
    __nv_bfloat16 (*Bs)[64][72] = (__nv_bfloat16(*)[64][72])(sm + 18432);
    float (*epi)[16][16]        = (float(*)[16][16])        (sm + 36864);
    uint32_t sA = smem_u32(sm), sB = sA + 18432u;

    int row0 = by * 64, col0 = bx * 64;
    const __nv_bfloat16* A = sel ? g_Wvfb : (g_Wqkvb + 2*DD);
    int lda = sel ? DD : W3;
    const __nv_bfloat16* B = sel ? g_Wfc2 : g_Wfc1b;
    int tid = threadIdx.x, w = tid >> 5, lane = tid & 31;
    int wm = w >> 2, wn = w & 3;

    wmma::fragment<wmma::accumulator,16,16,16,float> acc[2];
    #pragma unroll
    for (int i = 0; i < 2; i++) wmma::fill_fragment(acc[i], 0.f);

    #define W64_STAGE(kc, bb) {                                                    \
        _Pragma("unroll")                                                          \
        for (int r = 0; r < 2; r++) {                                              \
            int idx = tid + r*256;                                                 \
            int ar = idx >> 3, ac = (idx & 7) * 8;                                 \
            CPA16(sA + (uint32_t)(bb)*9216u + (uint32_t)ar*144u + (uint32_t)ac*2u, \
                  A + (size_t)(row0+ar)*lda + (kc) + ac);                          \
        }                                                                          \
        _Pragma("unroll")                                                          \
        for (int r = 0; r < 2; r++) {                                              \
            int idx = tid + r*256;                                                 \
            int br = idx >> 3, bc = (idx & 7) * 8;                                 \
            CPA16(sB + (uint32_t)(bb)*9216u + (uint32_t)br*144u + (uint32_t)bc*2u, \
                  B + (size_t)((kc)+br)*DD + col0 + bc);                           \
        }                                                                          \
        CPA_COMMIT(); }

    W64_STAGE(0, 0);
    for (int s = 0; s < 4; s++) {
        CPA_WAIT(0);
        __syncthreads();
        if (s < 3) W64_STAGE((s+1)*64, (s+1)&1);
        int bb = s & 1;
        #pragma unroll
        for (int k4 = 0; k4 < 4; k4++) {
            wmma::fragment<wmma::matrix_a,16,16,16,__nv_bfloat16,wmma::row_major> af[2];
            wmma::fragment<wmma::matrix_b,16,16,16,__nv_bfloat16,wmma::row_major> bf;
            #pragma unroll
            for (int i = 0; i < 2; i++)
                wmma::load_matrix_sync(af[i], &As[bb][wm*32 + i*16][k4*16], 72);
            wmma::load_matrix_sync(bf, &Bs[bb][k4*16][wn*16], 72);
            #pragma unroll
            for (int i = 0; i < 2; i++)
                wmma::mma_sync(acc[i], af[i], bf, acc[i]);
        }
    }
    #undef W64_STAGE
    __syncthreads();

    int r = lane >> 1, c8 = (lane & 1) * 8;
    #pragma unroll
    for (int i = 0; i < 2; i++) {
        wmma::store_matrix_sync(&epi[w][0][0], acc[i], 16, wmma::mem_row_major);
        __syncwarp();
        int gr = row0 + wm*32 + i*16 + r;
        int gc = col0 + wn*16 + c8;
        if (sel) {
            *(float4*)(g_Wvf2 + (size_t)gr*DD + gc)     = *(float4*)(&epi[w][r][c8]);
            *(float4*)(g_Wvf2 + (size_t)gr*DD + gc + 4) = *(float4*)(&epi[w][r][c8+4]);
        } else {
            __nv_bfloat16 t8[8];
            #pragma unroll
            for (int e = 0; e < 8; e++)
                t8[e] = __float2bfloat16(epi[w][r][c8+e]);
            *(uint4*)(g_Wvfb + (size_t)gr*DD + gc) = *(uint4*)t8;
        }
        __syncwarp();
    }
}

// ================= prep1: proj_agents || w64(0) || dbias || bvf ==============
__global__ void __launch_bounds__(256) prep1(const float* __restrict__ bqkv,
                                             const float* __restrict__ Wfc1,
                                             const float* __restrict__ bfc1) {
    extern __shared__ __align__(16) char sm[];
    int bid = blockIdx.x;
    if (bid < 8) {
        dev_proj_agents(sm, bid & 3, bid >> 2);
    } else if (bid < 24) {
        int t = bid - 8;
        dev_w64(sm, t & 3, t >> 2, 0);
    } else if (bid < 88) {
        float* red = (float*)sm;
        int a = bid - 24, i = threadIdx.x;
        red[i] = bqkv[i] * g_kaf[a*DD + i];
        __syncthreads();
        for (int st = 128; st > 0; st >>= 1) {
            if (i < st) red[i] += red[i + st];
            __syncthreads();
        }
        if (i == 0) g_dbias[a] = red[0];
    } else {
        int j = threadIdx.x;
        float t = bfc1[j];
        #pragma unroll 8
        for (int o = 0; o < DD; o++)
            t += bqkv[2*DD + o] * Wfc1[o*DD + j];
        g_bvf[j] = t;
    }
}

// ================= prep2: w64(1) || bvf2 =====================================
__global__ void __launch_bounds__(256) prep2(const float* __restrict__ Wfc2) {
    extern __shared__ __align__(16) char sm[];
    int bid = blockIdx.x;
    if (bid < 16) {
        dev_w64(sm, bid & 3, bid >> 2, 1);
    } else {
        int j = threadIdx.x;
        float t = 0.f;
        #pragma unroll 8
        for (int o = 0; o < DD; o++)
            t += g_bvf[o] * Wfc2[o*DD + j];
        g_bvf2[j] = t;
    }
}

// ======== fused stage-1 (SPL=32): logits[64,128] -> softmax -> u[64,256] ====
// smem: L[64][136]@0 (17408) | Qa 2x[64][40]@17408 (10240) | Ks 2x[128][40]@27648 (20480)
//       Vs 2x[32][264]@17408 overlay (33792, ends 51200) | epi@51200 (8192). total 59392
__global__ void __launch_bounds__(256) s1fused() {
    extern __shared__ __align__(16) char smf[];
    __nv_bfloat16 (*L)[136]      = ( __nv_bfloat16(*)[136]) smf;
    __nv_bfloat16 (*Qa)[64][40]  = ( __nv_bfloat16(*)[64][40]) (smf + 17408);
    __nv_bfloat16 (*Ks)[128][40] = ( __nv_bfloat16(*)[128][40])(smf + 27648);
    __nv_bfloat16 (*Vs)[32][264] = ( __nv_bfloat16(*)[32][264])(smf + 17408);
    float (*epi)[16][16]         = ( float(*)[16][16])         (smf + 51200);
    uint32_t sQ = smem_u32(smf) + 17408u;
    uint32_t sK = smem_u32(smf) + 27648u;
    uint32_t sV = smem_u32(smf) + 17408u;

    int split = blockIdx.x, b = blockIdx.y;
    int tok0 = split * TSPL;
    int tid = threadIdx.x;
    int w = tid >> 5, lane = tid & 31;
    int wm = w >> 2, wn = w & 3;

    // ---- pass 1: logits[64,128] ----
    #define F1_STAGE(kc, bb) {                                                     \
        {   int ar = tid >> 2, ac = (tid & 3) * 8;                                 \
            CPA16(sQ + (uint32_t)(bb)*5120u + (uint32_t)ar*80u + (uint32_t)ac*2u,  \
                  g_qap + (size_t)ar*DD + (kc) + ac); }                            \
        _Pragma("unroll")                                                          \
        for (int r = 0; r < 2; r++) {                                              \
            int idx = tid + r*256;                                                 \
            int kr = idx >> 2, kcc = (idx & 3) * 8;                                \
            CPA16(sK + (uint32_t)(bb)*10240u + (uint32_t)kr*80u + (uint32_t)kcc*2u,\
                  g_xb + (size_t)(b*NT + tok0 + kr)*DD + (kc) + kcc);              \
        }                                                                          \
        CPA_COMMIT(); }

    {
        wmma::fragment<wmma::accumulator,16,16,16,float> acc[2][2];
        #pragma unroll
        for (int i = 0; i < 2; i++)
            #pragma unroll
            for (int j = 0; j < 2; j++) wmma::fill_fragment(acc[i][j], 0.f);

        F1_STAGE(0, 0);
        for (int s = 0; s < 8; s++) {
            CPA_WAIT(0);
            __syncthreads();
            if (s < 7) F1_STAGE((s+1)*32, (s+1)&1);
            int bb = s & 1;
            #pragma unroll
            for (int kk = 0; kk < 2; kk++) {
                wmma::fragment<wmma::matrix_a,16,16,16,__nv_bfloat16,wmma::row_major> af[2];
                wmma::fragment<wmma::matrix_b,16,16,16,__nv_bfloat16,wmma::col_major> bf[2];
                #pragma unroll
                for (int i = 0; i < 2; i++)
                    wmma::load_matrix_sync(af[i], &Qa[bb][wm*32 + i*16][kk*16], 40);
                #pragma unroll
                for (int j = 0; j < 2; j++)
                    wmma::load_matrix_sync(bf[j], &Ks[bb][wn*32 + j*16][kk*16], 40);
                #pragma unroll
                for (int i = 0; i < 2; i++)
                    #pragma unroll
                    for (int j = 0; j < 2; j++)
                        wmma::mma_sync(acc[i][j], af[i], bf[j], acc[i][j]);
            }
        }
        __syncthreads();
        #pragma unroll
        for (int i = 0; i < 2; i++)
            #pragma unroll
            for (int j = 0; j < 2; j++) {
                wmma::store_matrix_sync(&epi[w][0][0], acc[i][j], 16, wmma::mem_row_major);
                __syncwarp();
                if (lane < 16) {
                    int ga = wm*32 + i*16 + lane;
                    int gc = wn*32 + j*16;
                    __nv_bfloat16 t8[8];
                    #pragma unroll
                    for (int g = 0; g < 2; g++) {
                        #pragma unroll
                        for (int e = 0; e < 8; e++)
                            t8[e] = __float2bfloat16(epi[w][lane][g*8+e]);
                        *(uint4*)(&L[ga][gc + g*8]) = *(uint4*)t8;
                    }
                }
                __syncwarp();
            }
        __syncthreads();
    }
    #undef F1_STAGE

    // ---- split softmax over 128 cols: row = tid>>2, 4 threads/row (32 each) ----
    {
        int row = tid >> 2, q = tid & 3;
        float m = -1e30f;
        #pragma unroll 8
        for (int c = 0; c < 32; c++)
            m = fmaxf(m, __bfloat162float(L[row][q*32 + c]));
        m = fmaxf(m, __shfl_xor_sync(0xffffffffu, m, 1));
        m = fmaxf(m, __shfl_xor_sync(0xffffffffu, m, 2));
        float sum = 0.f;
        #pragma unroll 8
        for (int c = 0; c < 32; c++) {
            float p = __expf(__bfloat162float(L[row][q*32 + c]) - m);
            sum += p;
            L[row][q*32 + c] = __float2bfloat16(p);
        }
        sum += __shfl_xor_sync(0xffffffffu, sum, 1);
        sum += __shfl_xor_sync(0xffffffffu, sum, 2);
        if (q == 0)
            g_stats[(b*SPL + split)*NA + row] = make_float2(m, sum);
    }
    __syncthreads();

    // ---- pass 2: u_split[64,256] = P[64,128] @ x_split[128,256] ----
    {
        wmma::fragment<wmma::accumulator,16,16,16,float> acc[2][4];
        #pragma unroll
        for (int i = 0; i < 2; i++)
            #pragma unroll
            for (int j = 0; j < 4; j++) wmma::fill_fragment(acc[i][j], 0.f);

        #define F2_STAGE(kc, bb) {                                                 \
            _Pragma("unroll")                                                      \
            for (int r = 0; r < 4; r++) {                                          \
                int idx = tid + r*256;                                             \
                int vr = idx >> 5, vc = (idx & 31) * 8;                            \
                CPA16(sV + (uint32_t)(bb)*16896u + (uint32_t)vr*528u + (uint32_t)vc*2u,\
                      g_xb + (size_t)(b*NT + tok0 + (kc) + vr)*DD + vc);           \
            }                                                                      \
            CPA_COMMIT(); }

        F2_STAGE(0, 0);
        for (int s = 0; s < 4; s++) {
            CPA_WAIT(0);
            __syncthreads();
            if (s < 3) F2_STAGE((s+1)*32, (s+1)&1);
            int bb = s & 1;
            #pragma unroll
            for (int kk = 0; kk < 2; kk++) {
                wmma::fragment<wmma::matrix_a,16,16,16,__nv_bfloat16,wmma::row_major> af[2];
                wmma::fragment<wmma::matrix_b,16,16,16,__nv_bfloat16,wmma::row_major> bf[4];
                #pragma unroll
                for (int i = 0; i < 2; i++)
                    wmma::load_matrix_sync(af[i], &L[wm*32 + i*16][s*32 + kk*16], 136);
                #pragma unroll
                for (int j = 0; j < 4; j++)
                    wmma::load_matrix_sync(bf[j], &Vs[bb][kk*16][wn*64 + j*16], 264);
                #pragma unroll
                for (int i = 0; i < 2; i++)
                    #pragma unroll
                    for (int j = 0; j < 4; j++)
                        wmma::mma_sync(acc[i][j], af[i], bf[j], acc[i][j]);
            }
        }
        #undef F2_STAGE
        __syncthreads();

        float* outb = g_vap + (size_t)(b*SPL + split)*NA*DD;
        #pragma unroll
        for (int i = 0; i < 2; i++)
            #pragma unroll
            for (int j = 0; j < 4; j++) {
                wmma::store_matrix_sync(&epi[w][0][0], acc[i][j], 16, wmma::mem_row_major);
                __syncwarp();
                #pragma unroll
                for (int e = 0; e < 2; e++) {
                    int idx2 = lane + e*32;
                    int r = idx2 >> 2, c4 = (idx2 & 3) * 4;
                    int ga = wm*32 + i*16 + r;
                    int gd = wn*64 + j*16 + c4;
                    *(float4*)(outb + (size_t)ga*DD + gd) = *(float4*)(&epi[w][r][c4]);
                }
                __syncwarp();
            }
    }
}

// ---------------- fc1: combine splits (rescale), then va2 = u @ Wvf2 + bvf2 --
__global__ void fc1k() {
    __shared__ float r0[DD];
    __shared__ float ms[SPL], ss[SPL];
    int row = blockIdx.x;  // b*NA + a
    int b = row >> 6, a = row & 63;
    int i = threadIdx.x;

    if (i < SPL) {
        float2 st = g_stats[(b*SPL + i)*NA + a];
        ms[i] = st.x; ss[i] = st.y;
    }
    __syncthreads();
    float m = -1e30f;
    #pragma unroll
    for (int s = 0; s < SPL; s++) m = fmaxf(m, ms[s]);
    float S = 0.f;
    float wsc[SPL];
    #pragma unroll
    for (int s = 0; s < SPL; s++) {
        wsc[s] = __expf(ms[s] - m);
        S += wsc[s] * ss[s];
    }
    float acc = 0.f;
    #pragma unroll
    for (int s = 0; s < SPL; s++)
        acc += wsc[s] * g_vap[(size_t)(b*SPL + s)*NA*DD + (size_t)a*DD + i];
    r0[i] = acc / S;
    __syncthreads();
    int o = threadIdx.x;
    float sum = g_bvf2[o];
    #pragma unroll 8
    for (int d = 0; d < DD; d++) sum += r0[d] * g_Wvf2[d*DD + o];
    g_va[(size_t)row*DD + o] = __float2bfloat16(sum);
}

// ======== stage 2 (64-token tiles): logits -> softmax -> P@va2 + bfc2 + x ====
__global__ void __launch_bounds__(256) stage2(const float* __restrict__ bfc2,
                                              const float* __restrict__ x,
                                              float* __restrict__ out) {
    extern __shared__ __align__(16) char sm2[];
    __nv_bfloat16 (*Qs)[64][40] = ( __nv_bfloat16(*)[64][40]) sm2;
    __nv_bfloat16 (*Ka)[64][40] = ( __nv_bfloat16(*)[64][40]) (sm2 + 10240);
    float* logits               = ( float*)                   (sm2 + 20480);
    __nv_bfloat16 (*Vs)[264]    = ( __nv_bfloat16(*)[264])    (sm2 + 37888);
    __nv_bfloat16 (*Pm)[72]     = ( __nv_bfloat16(*)[72])     sm2;
    float (*epi)[16][16]        = ( float(*)[16][16])         (sm2 + 10240);
    __shared__ float dbs[NA];
    uint32_t sQ = smem_u32(sm2), sKa = sQ + 10240u, sV = sQ + 37888u;

    int b = blockIdx.y, t0 = blockIdx.x * 64;
    int tid = threadIdx.x;
    int w = tid >> 5, lane = tid & 31;
    int wm = w >> 2, wn = w & 3;

    if (tid < NA) dbs[tid] = g_dbias[tid];

    #pragma unroll
    for (int r = 0; r < 8; r++) {
        int idx = tid + r*256;
        int vr = idx >> 5, vc = (idx & 31) * 8;
        CPA16(sV + (uint32_t)vr*528u + (uint32_t)vc*2u,
              g_va + (size_t)(b*NA + vr)*DD + vc);
    }
    CPA_COMMIT();

    // --- phase A: logits[64,64] = x_tile[64,256] @ Ka'[64,256]^T ---
    {
        wmma::fragment<wmma::accumulator,16,16,16,float> acc[2];
        #pragma unroll
        for (int i = 0; i < 2; i++) wmma::fill_fragment(acc[i], 0.f);

        #define S2_STAGE(kc, bb) {                                                 \
            {   int qr = tid >> 2, qc = (tid & 3) * 8;                             \
                CPA16(sQ + (uint32_t)(bb)*5120u + (uint32_t)qr*80u + (uint32_t)qc*2u, \
                      g_xb + (size_t)(b*NT + t0 + qr)*DD + (kc) + qc); }           \
            {   int ar = tid >> 2, ac = (tid & 3) * 8;                             \
                CPA16(sKa + (uint32_t)(bb)*5120u + (uint32_t)ar*80u + (uint32_t)ac*2u, \
                      g_kat + (size_t)ar*DD + (kc) + ac); }                        \
            CPA_COMMIT(); }

        S2_STAGE(0, 0);
        for (int s = 0; s < 8; s++) {
            CPA_WAIT(0);
            __syncthreads();
            if (s < 7) S2_STAGE((s+1)*32, (s+1)&1);
            int bb = s & 1;
            #pragma unroll
            for (int kk = 0; kk < 2; kk++) {
                wmma::fragment<wmma::matrix_a,16,16,16,__nv_bfloat16,wmma::row_major> af[2];
                wmma::fragment<wmma::matrix_b,16,16,16,__nv_bfloat16,wmma::col_major> bf;
                #pragma unroll
                for (int i = 0; i < 2; i++)
                    wmma::load_matrix_sync(af[i], &Qs[bb][wm*32 + i*16][kk*16], 40);
                wmma::load_matrix_sync(bf, &Ka[bb][wn*16][kk*16], 40);
                #pragma unroll
                for (int i = 0; i < 2; i++)
                    wmma::mma_sync(acc[i], af[i], bf, acc[i]);
            }
        }
        #undef S2_STAGE
        __syncthreads();
        #pragma unroll
        for (int i = 0; i < 2; i++)
            wmma::store_matrix_sync(logits + (wm*32 + i*16)*68 + wn*16,
                                    acc[i], 68, wmma::mem_row_major);
    }
    __syncthreads();

    // --- phase B: per-row softmax over 64 agents (+dbias); 4 threads/row ---
    {
        int row = tid >> 2, q = tid & 3;
        const float* lr = logits + row*68 + q*16;
        float lv[16];
        #pragma unroll
        for (int c = 0; c < 16; c++) lv[c] = lr[c] + dbs[q*16 + c];
        float m = -1e30f;
        #pragma unroll
        for (int c = 0; c < 16; c++) m = fmaxf(m, lv[c]);
        m = fmaxf(m, __shfl_xor_sync(0xffffffffu, m, 1));
        m = fmaxf(m, __shfl_xor_sync(0xffffffffu, m, 2));
        float sum = 0.f;
        float pv[16];
        #pragma unroll
        for (int c = 0; c < 16; c++) { pv[c] = __expf(lv[c] - m); sum += pv[c]; }
        sum += __shfl_xor_sync(0xffffffffu, sum, 1);
        sum += __shfl_xor_sync(0xffffffffu, sum, 2);
        float inv = 1.f / sum;
        __syncthreads();
        #pragma unroll
        for (int c = 0; c < 16; c++)
            Pm[row][q*16 + c] = __float2bfloat16(pv[c] * inv);
    }
    __syncthreads();

    // --- phase C: out[64,256] = Pm[64,64] @ Vs[64,256] + bfc2 + x ---
    {
        wmma::fragment<wmma::accumulator,16,16,16,float> acc[2][4];
        #pragma unroll
        for (int i = 0; i < 2; i++)
            #pragma unroll
            for (int j = 0; j < 4; j++) wmma::fill_fragment(acc[i][j], 0.f);
        #pragma unroll
        for (int kk = 0; kk < 4; kk++) {
            wmma::fragment<wmma::matrix_a,16,16,16,__nv_bfloat16,wmma::row_major> af[2];
            wmma::fragment<wmma::matrix_b,16,16,16,__nv_bfloat16,wmma::row_major> bf[4];
            #pragma unroll
            for (int i = 0; i < 2; i++)
                wmma::load_matrix_sync(af[i], &Pm[wm*32 + i*16][kk*16], 72);
            #pragma unroll
            for (int j = 0; j < 4; j++)
                wmma::load_matrix_sync(bf[j], &Vs[kk*16][wn*64 + j*16], 264);
            #pragma unroll
            for (int i = 0; i < 2; i++)
                #pragma unroll
                for (int j = 0; j < 4; j++)
                    wmma::mma_sync(acc[i][j], af[i], bf[j], acc[i][j]);
        }
        __syncthreads();
        int r = lane >> 1, c8 = (lane & 1) * 8;
        #pragma unroll
        for (int i = 0; i < 2; i++)
            #pragma unroll
            for (int j = 0; j < 4; j++) {
                wmma::store_matrix_sync(&epi[w][0][0], acc[i][j], 16, wmma::mem_row_major);
                __syncwarp();
                int grow = t0 + wm*32 + i*16 + r;
                int gcol = wn*64 + j*16 + c8;
                size_t gi = (size_t)(b*NT + grow)*DD + gcol;
                float o0[4], o1[4];
                #pragma unroll
                for (int e = 0; e < 4; e++)
                    o0[e] = epi[w][r][c8+e]   + bfc2[gcol+e]   + x[gi+e];
                #pragma unroll
                for (int e = 0; e < 4; e++)
                    o1[e] = epi[w][r][c8+4+e] + bfc2[gcol+4+e] + x[gi+4+e];
                *(float4*)(out + gi)     = *(float4*)o0;
                *(float4*)(out + gi + 4) = *(float4*)o1;
                __syncwarp();
            }
    }
}

// ---------------- launcher ---------------------------------------------------
#define S1F_SMEM 59392
#define S2_SMEM  71680
#define PREP_SMEM 45056

extern "C" void kernel_launch(void* const* d_in, const int* in_sizes, int n_in,
                              void* d_out, int out_size) {
    const float* agent = (const float*)d_in[0];
    const float* x     = (const float*)d_in[1];
    const float* Wqkv  = (const float*)d_in[2];
    const float* bqkv  = (const float*)d_in[3];
    const float* Wag   = (const float*)d_in[4];
    const float* bag   = (const float*)d_in[5];
    const float* Wfc1  = (const float*)d_in[6];
    const float* bfc1  = (const float*)d_in[7];
    const float* Wfc2  = (const float*)d_in[8];
    const float* bfc2  = (const float*)d_in[9];
    float* out = (float*)d_out;

    cudaFuncSetAttribute(s1fused, cudaFuncAttributeMaxDynamicSharedMemorySize, S1F_SMEM);
    cudaFuncSetAttribute(stage2,  cudaFuncAttributeMaxDynamicSharedMemorySize, S2_SMEM);

    prep0<<<1088, 512>>>(x, Wfc2, Wqkv, Wfc1, agent, Wag, bag);
    prep1<<<89, 256, PREP_SMEM>>>(bqkv, Wfc1, bfc1);
    prep2<<<17, 256, PREP_SMEM>>>(Wfc2);
    s1fused<<<dim3(SPL, NB), 256, S1F_SMEM>>>();
    fc1k<<<512, 256>>>();
    stage2<<<dim3(64, 8), 256, S2_SMEM>>>(bfc2, x, out);
}

// round 13
// speedup vs baseline: 1.0479x; 1.0479x over previous
#include <cuda_runtime.h>
#include <cuda_bf16.h>
#include <mma.h>
#include <cstdint>

using namespace nvcuda;

#define NB 8
#define NT 4096
#define NA 64
#define DD 256
#define MTOK (NB*NT)
#define W3 (3*DD)
#define SPL 32
#define TSPL 128   // tokens per split

// ---------------- scratch (device globals; no allocations allowed) ----------
__device__ __nv_bfloat16 g_xb[MTOK*DD];              // x in bf16
__device__ __nv_bfloat16 g_Wqkvb[DD*W3];             // W_qkv bf16 [K, 3N]
__device__ __nv_bfloat16 g_Wffb[DD*DD];              // Wfc1@Wfc2 bf16
__device__ __nv_bfloat16 g_qasb[NA*DD];              // qa_s bf16 (scale folded)
__device__ __nv_bfloat16 g_kasb[NA*DD];              // ka_s bf16 (scale folded)
__device__ float        g_kaf[NA*DD];                // ka_s fp32 (for dbias)
__device__ __nv_bfloat16 g_qap[NA*DD];               // qa' = qa_s @ Wk^T, bf16
__device__ __nv_bfloat16 g_kat[NA*DD];               // Ka' [a,i] bf16
__device__ float        g_dbias[NA];                 // bq . ka_s
__device__ float        g_Wvf2[DD*DD];               // Wv@(Wfc1@Wfc2), fp32
__device__ float        g_bvf2[DD];                  // (bv@Wfc1+bfc1)@Wfc2
__device__ __nv_bfloat16 g_vapb[NB*SPL*NA*DD];       // unnormalized split partials (bf16)
__device__ float2       g_stats[NB*SPL*NA];          // (m_s, s_s) per split-row
__device__ __nv_bfloat16 g_va[NB*NA*DD];             // va2 bf16

// ---------------- cp.async helpers ------------------------------------------
__device__ __forceinline__ uint32_t smem_u32(const void* p) {
    uint32_t a;
    asm("{ .reg .u64 t; cvta.to.shared.u64 t, %1; cvt.u32.u64 %0, t; }" : "=r"(a) : "l"(p));
    return a;
}
#define CPA16(s, g)  asm volatile("cp.async.cg.shared.global [%0], [%1], 16;" :: "r"(s), "l"(g))
#define CPA_COMMIT() asm volatile("cp.async.commit_group;" ::: "memory")
#define CPA_WAIT(n)  asm volatile("cp.async.wait_group %0;" :: "n"(n) : "memory")

// ---------------- device: Wff tile = Wfc1@Wfc2 (fp32 src, 512 threads) -------
// smem: As[64][72] @0 (9216) | Bs[64][72] @9216 (9216) | epi[8][16][16] @18432
__device__ void dev_wff(char* sm, int bx, int by,
                        const float* __restrict__ A, const float* __restrict__ B) {
    __nv_bfloat16 (*As)[72] = (__nv_bfloat16(*)[72]) sm;
    __nv_bfloat16 (*Bs)[72] = (__nv_bfloat16(*)[72])(sm + 9216);
    float (*epi)[16][16]    = (float(*)[16][16])    (sm + 18432);
    int row0 = by*64, col0 = bx*64;
    int tid = threadIdx.x, w = tid >> 5, lane = tid & 31;
    int wm = w >> 2, wn = w & 3;   // valid for w < 8

    wmma::fragment<wmma::accumulator,16,16,16,float> acc[2];
    #pragma unroll
    for (int i = 0; i < 2; i++) wmma::fill_fragment(acc[i], 0.f);

    for (int kc = 0; kc < 4; kc++) {
        #pragma unroll
        for (int r = 0; r < 2; r++) {
            int idx = tid + r*512;
            int ar = idx >> 4, ac = (idx & 15) * 4;
            float4 va4 = *(const float4*)(A + (size_t)(row0+ar)*DD + kc*64 + ac);
            __nv_bfloat16 ta[4] = {__float2bfloat16(va4.x), __float2bfloat16(va4.y),
                                   __float2bfloat16(va4.z), __float2bfloat16(va4.w)};
            *(uint2*)(&As[ar][ac]) = *(uint2*)ta;
            float4 vb4 = *(const float4*)(B + (size_t)(kc*64+ar)*DD + col0 + ac);
            __nv_bfloat16 tb[4] = {__float2bfloat16(vb4.x), __float2bfloat16(vb4.y),
                                   __float2bfloat16(vb4.z), __float2bfloat16(vb4.w)};
            *(uint2*)(&Bs[ar][ac]) = *(uint2*)tb;
        }
        __syncthreads();
        if (w < 8) {
            #pragma unroll
            for (int k4 = 0; k4 < 4; k4++) {
                wmma::fragment<wmma::matrix_a,16,16,16,__nv_bfloat16,wmma::row_major> af[2];
                wmma::fragment<wmma::matrix_b,16,16,16,__nv_bfloat16,wmma::row_major> bf;
                #pragma unroll
                for (int i = 0; i < 2; i++)
                    wmma::load_matrix_sync(af[i], &As[wm*32 + i*16][k4*16], 72);
                wmma::load_matrix_sync(bf, &Bs[k4*16][wn*16], 72);
                #pragma unroll
                for (int i = 0; i < 2; i++)
                    wmma::mma_sync(acc[i], af[i], bf, acc[i]);
            }
        }
        __syncthreads();
    }
    if (w < 8) {
        int r = lane >> 1, c8 = (lane & 1) * 8;
        #pragma unroll
        for (int i = 0; i < 2; i++) {
            wmma::store_matrix_sync(&epi[w][0][0], acc[i], 16, wmma::mem_row_major);
            __syncwarp();
            int gr = row0 + wm*32 + i*16 + r;
            int gc = col0 + wn*16 + c8;
            __nv_bfloat16 t8[8];
            #pragma unroll
            for (int e = 0; e < 8; e++)
                t8[e] = __float2bfloat16(epi[w][r][c8+e]);
            *(uint4*)(g_Wffb + (size_t)gr*DD + gc) = *(uint4*)t8;
            __syncwarp();
        }
    }
}

// ================= prep0: conv(x, Wqkv) || agent_proj || Wff ================
// grid 1104 x 512 threads, dyn smem 45056
__global__ void __launch_bounds__(512) prep0(const float* __restrict__ x,
                                             const float* __restrict__ Wqkv,
                                             const float* __restrict__ Wfc1,
                                             const float* __restrict__ Wfc2,
                                             const float* __restrict__ agent,
                                             const float* __restrict__ Wag,
                                             const float* __restrict__ bag) {
    extern __shared__ __align__(16) char smp[];
    if (blockIdx.x < 1024) {
        int tid = blockIdx.x * 512 + threadIdx.x;
        int stride = 1024 * 512;
        for (int i = tid; i < (MTOK*DD)/4; i += stride) {
            float4 v = *(const float4*)(x + i*4);
            __nv_bfloat16 t[4] = {__float2bfloat16(v.x), __float2bfloat16(v.y),
                                  __float2bfloat16(v.z), __float2bfloat16(v.w)};
            *(uint2*)(g_xb + i*4) = *(uint2*)t;
        }
        for (int i = tid; i < DD*W3; i += stride)
            g_Wqkvb[i] = __float2bfloat16(Wqkv[i]);
    } else if (blockIdx.x < 1088) {
        __shared__ float arow[DD];
        int a = blockIdx.x - 1024;
        for (int i = threadIdx.x; i < DD; i += 512)
            arow[i] = agent[a*DD + i];
        __syncthreads();
        int o = threadIdx.x;  // 0..511
        float s = 0.f;
        #pragma unroll 8
        for (int d = 0; d < DD; d++)
            s += arow[d] * Wag[d*2*DD + o];
        s += bag[o];
        s *= 0.0625f;  // 256^-0.5
        if (o < DD) {
            g_qasb[a*DD + o] = __float2bfloat16(s);
        } else {
            g_kasb[a*DD + (o-DD)] = __float2bfloat16(s);
            g_kaf [a*DD + (o-DD)] = s;
        }
    } else {
        int t = blockIdx.x - 1088;
        dev_wff(smp, t & 3, t >> 2, Wfc1, Wfc2);
    }
}

// ---------------- device: proj_agents tile (256 thr) -------------------------
__device__ void dev_proj_agents(char* sm, int ix, int sel) {
    __nv_bfloat16 (*Aa)[64][40] = (__nv_bfloat16(*)[64][40]) sm;
    __nv_bfloat16 (*Ws)[64][40] = (__nv_bfloat16(*)[64][40])(sm + 10240);
    float (*epi)[16][16]        = (float(*)[16][16])        (sm + 20480);
    uint32_t sA = smem_u32(sm), sW = sA + 10240u;

    int col0 = ix * 64;
    const __nv_bfloat16* A  = sel ? g_kasb : g_qasb;
    const __nv_bfloat16* Bb = g_Wqkvb + (sel ? 0 : DD);
    __nv_bfloat16* C = sel ? g_kat : g_qap;
    int tid = threadIdx.x;
    int w = tid >> 5, lane = tid & 31;
    int wm = w >> 2, wn = w & 3;

    wmma::fragment<wmma::accumulator,16,16,16,float> acc[2];
    #pragma unroll
    for (int i = 0; i < 2; i++) wmma::fill_fragment(acc[i], 0.f);

    #define PA_STAGE(kc, bb) {                                                     \
        {   int ar = tid >> 2, ac = (tid & 3) * 8;                                 \
            CPA16(sA + (uint32_t)(bb)*5120u + (uint32_t)ar*80u + (uint32_t)ac*2u,  \
                  A + (size_t)ar*DD + (kc) + ac); }                                \
        {   int wr = tid >> 2, wc = (tid & 3) * 8;                                 \
            CPA16(sW + (uint32_t)(bb)*5120u + (uint32_t)wr*80u + (uint32_t)wc*2u,  \
                  Bb + (size_t)(col0 + wr)*W3 + (kc) + wc); }                      \
        CPA_COMMIT(); }

    PA_STAGE(0, 0);
    for (int s = 0; s < 8; s++) {
        CPA_WAIT(0);
        __syncthreads();
        if (s < 7) PA_STAGE((s+1)*32, (s+1)&1);
        int bb = s & 1;
        #pragma unroll
        for (int kk = 0; kk < 2; kk++) {
            wmma::fragment<wmma::matrix_a,16,16,16,__nv_bfloat16,wmma::row_major> af[2];
            wmma::fragment<wmma::matrix_b,16,16,16,__nv_bfloat16,wmma::col_major> bf;
            #pragma unroll
            for (int i = 0; i < 2; i++)
                wmma::load_matrix_sync(af[i], &Aa[bb][wm*32 + i*16][kk*16], 40);
            wmma::load_matrix_sync(bf, &Ws[bb][wn*16][kk*16], 40);
            #pragma unroll
            for (int i = 0; i < 2; i++)
                wmma::mma_sync(acc[i], af[i], bf, acc[i]);
        }
    }
    #undef PA_STAGE

    #pragma unroll
    for (int i = 0; i < 2; i++) {
        wmma::store_matrix_sync(&epi[w][0][0], acc[i], 16, wmma::mem_row_major);
        __syncwarp();
        if (lane < 16) {
            int a = wm*32 + i*16 + lane;
            __nv_bfloat16 t8[8];
            #pragma unroll
            for (int g = 0; g < 2; g++) {
                #pragma unroll
                for (int e = 0; e < 8; e++)
                    t8[e] = __float2bfloat16(epi[w][lane][g*8+e]);
                *(uint4*)(C + (size_t)a*DD + col0 + wn*16 + g*8) = *(uint4*)t8;
            }
        }
        __syncwarp();
    }
}

// ---------------- device: Wvf2 tile = Wv @ Wffb (cp.async, f32 out) ----------
__device__ void dev_wvf2(char* sm, int bx, int by) {
    __nv_bfloat16 (*As)[64][72] = (__nv_bfloat16(*)[64][72]) sm;
    __nv_bfloat16 (*Bs)[64][72] = (__nv_bfloat16(*)[64][72])(sm + 18432);
    float (*epi)[16][16]        = (float(*)[16][16])        (sm + 36864);
    uint32_t sA = smem_u32(sm), sB = sA + 18432u;

    int row0 = by * 64, col0 = bx * 64;
    const __nv_bfloat16* A = g_Wqkvb + 2*DD;   // Wv rows, lda = W3
    const __nv_bfloat16* B = g_Wffb;           // lda = DD
    int tid = threadIdx.x, w = tid >> 5, lane = tid & 31;
    int wm = w >> 2, wn = w & 3;

    wmma::fragment<wmma::accumulator,16,16,16,float> acc[2];
    #pragma unroll
    for (int i = 0; i < 2; i++) wmma::fill_fragment(acc[i], 0.f);

    #define WV_STAGE(kc, bb) {                                                     \
        _Pragma("unroll")                                                          \
        for (int r = 0; r < 2; r++) {                                              \
            int idx = tid + r*256;                                                 \
            int ar = idx >> 3, ac = (idx & 7) * 8;                                 \
            CPA16(sA + (uint32_t)(bb)*9216u + (uint32_t)ar*144u + (uint32_t)ac*2u, \
                  A + (size_t)(row0+ar)*W3 + (kc) + ac);                           \
        }                                                                          \
        _Pragma("unroll")                                                          \
        for (int r = 0; r < 2; r++) {                                              \
            int idx = tid + r*256;                                                 \
            int br = idx >> 3, bc = (idx & 7) * 8;                                 \
            CPA16(sB + (uint32_t)(bb)*9216u + (uint32_t)br*144u + (uint32_t)bc*2u, \
                  B + (size_t)((kc)+br)*DD + col0 + bc);                           \
        }                                                                          \
        CPA_COMMIT(); }

    WV_STAGE(0, 0);
    for (int s = 0; s < 4; s++) {
        CPA_WAIT(0);
        __syncthreads();
        if (s < 3) WV_STAGE((s+1)*64, (s+1)&1);
        int bb = s & 1;
        #pragma unroll
        for (int k4 = 0; k4 < 4; k4++) {
            wmma::fragment<wmma::matrix_a,16,16,16,__nv_bfloat16,wmma::row_major> af[2];
            wmma::fragment<wmma::matrix_b,16,16,16,__nv_bfloat16,wmma::row_major> bf;
            #pragma unroll
            for (int i = 0; i < 2; i++)
                wmma::load_matrix_sync(af[i], &As[bb][wm*32 + i*16][k4*16], 72);
            wmma::load_matrix_sync(bf, &Bs[bb][k4*16][wn*16], 72);
            #pragma unroll
            for (int i = 0; i < 2; i++)
                wmma::mma_sync(acc[i], af[i], bf, acc[i]);
        }
    }
    #undef WV_STAGE
    __syncthreads();

    int r = lane >> 1, c8 = (lane & 1) * 8;
    #pragma unroll
    for (int i = 0; i < 2; i++) {
        wmma::store_matrix_sync(&epi[w][0][0], acc[i], 16, wmma::mem_row_major);
        __syncwarp();
        int gr = row0 + wm*32 + i*16 + r;
        int gc = col0 + wn*16 + c8;
        *(float4*)(g_Wvf2 + (size_t)gr*DD + gc)     = *(float4*)(&epi[w][r][c8]);
        *(float4*)(g_Wvf2 + (size_t)gr*DD + gc + 4) = *(float4*)(&epi[w][r][c8+4]);
        __syncwarp();
    }
}

// ===== prep1: proj_agents || Wvf2 || dbias || bvf2 (grid 89, 256 thr) ========
__global__ void __launch_bounds__(256) prep1(const float* __restrict__ bqkv,
                                             const float* __restrict__ Wfc1,
                                             const float* __restrict__ bfc1,
                                             const float* __restrict__ Wfc2) {
    extern __shared__ __align__(16) char sm[];
    int bid = blockIdx.x;
    if (bid < 8) {
        dev_proj_agents(sm, bid & 3, bid >> 2);
    } else if (bid < 24) {
        int t = bid - 8;
        dev_wvf2(sm, t & 3, t >> 2);
    } else if (bid < 88) {
        float* red = (float*)sm;
        int a = bid - 24, i = threadIdx.x;
        red[i] = bqkv[i] * g_kaf[a*DD + i];
        __syncthreads();
        for (int st = 128; st > 0; st >>= 1) {
            if (i < st) red[i] += red[i + st];
            __syncthreads();
        }
        if (i == 0) g_dbias[a] = red[0];
    } else {
        // bvf2 = (bv@Wfc1 + bfc1) @ Wfc2, two chained GEMVs
        float* bvf = (float*)sm;
        int j = threadIdx.x;
        float t = bfc1[j];
        #pragma unroll 8
        for (int o = 0; o < DD; o++)
            t += bqkv[2*DD + o] * Wfc1[o*DD + j];
        bvf[j] = t;
        __syncthreads();
        float t2 = 0.f;
        #pragma unroll 8
        for (int o = 0; o < DD; o++)
            t2 += bvf[o] * Wfc2[o*DD + j];
        g_bvf2[j] = t2;
    }
}

// ======== fused stage-1 (SPL=32): logits[64,128] -> softmax -> u[64,256] ====
__global__ void __launch_bounds__(256) s1fused() {
    extern __shared__ __align__(16) char smf[];
    __nv_bfloat16 (*L)[136]      = ( __nv_bfloat16(*)[136]) smf;
    __nv_bfloat16 (*Qa)[64][40]  = ( __nv_bfloat16(*)[64][40]) (smf + 17408);
    __nv_bfloat16 (*Ks)[128][40] = ( __nv_bfloat16(*)[128][40])(smf + 27648);
    __nv_bfloat16 (*Vs)[32][264] = ( __nv_bfloat16(*)[32][264])(smf + 17408);
    float (*epi)[16][16]         = ( float(*)[16][16])         (smf + 51200);
    uint32_t sQ = smem_u32(smf) + 17408u;
    uint32_t sK = smem_u32(smf) + 27648u;
    uint32_t sV = smem_u32(smf) + 17408u;

    int split = blockIdx.x, b = blockIdx.y;
    int tok0 = split * TSPL;
    int tid = threadIdx.x;
    int w = tid >> 5, lane = tid & 31;
    int wm = w >> 2, wn = w & 3;

    // ---- pass 1: logits[64,128] ----
    #define F1_STAGE(kc, bb) {                                                     \
        {   int ar = tid >> 2, ac = (tid & 3) * 8;                                 \
            CPA16(sQ + (uint32_t)(bb)*5120u + (uint32_t)ar*80u + (uint32_t)ac*2u,  \
                  g_qap + (size_t)ar*DD + (kc) + ac); }                            \
        _Pragma("unroll")                                                          \
        for (int r = 0; r < 2; r++) {                                              \
            int idx = tid + r*256;                                                 \
            int kr = idx >> 2, kcc = (idx & 3) * 8;                                \
            CPA16(sK + (uint32_t)(bb)*10240u + (uint32_t)kr*80u + (uint32_t)kcc*2u,\
                  g_xb + (size_t)(b*NT + tok0 + kr)*DD + (kc) + kcc);              \
        }                                                                          \
        CPA_COMMIT(); }

    {
        wmma::fragment<wmma::accumulator,16,16,16,float> acc[2][2];
        #pragma unroll
        for (int i = 0; i < 2; i++)
            #pragma unroll
            for (int j = 0; j < 2; j++) wmma::fill_fragment(acc[i][j], 0.f);

        F1_STAGE(0, 0);
        for (int s = 0; s < 8; s++) {
            CPA_WAIT(0);
            __syncthreads();
            if (s < 7) F1_STAGE((s+1)*32, (s+1)&1);
            int bb = s & 1;
            #pragma unroll
            for (int kk = 0; kk < 2; kk++) {
                wmma::fragment<wmma::matrix_a,16,16,16,__nv_bfloat16,wmma::row_major> af[2];
                wmma::fragment<wmma::matrix_b,16,16,16,__nv_bfloat16,wmma::col_major> bf[2];
                #pragma unroll
                for (int i = 0; i < 2; i++)
                    wmma::load_matrix_sync(af[i], &Qa[bb][wm*32 + i*16][kk*16], 40);
                #pragma unroll
                for (int j = 0; j < 2; j++)
                    wmma::load_matrix_sync(bf[j], &Ks[bb][wn*32 + j*16][kk*16], 40);
                #pragma unroll
                for (int i = 0; i < 2; i++)
                    #pragma unroll
                    for (int j = 0; j < 2; j++)
                        wmma::mma_sync(acc[i][j], af[i], bf[j], acc[i][j]);
            }
        }
        __syncthreads();
        #pragma unroll
        for (int i = 0; i < 2; i++)
            #pragma unroll
            for (int j = 0; j < 2; j++) {
                wmma::store_matrix_sync(&epi[w][0][0], acc[i][j], 16, wmma::mem_row_major);
                __syncwarp();
                if (lane < 16) {
                    int ga = wm*32 + i*16 + lane;
                    int gc = wn*32 + j*16;
                    __nv_bfloat16 t8[8];
                    #pragma unroll
                    for (int g = 0; g < 2; g++) {
                        #pragma unroll
                        for (int e = 0; e < 8; e++)
                            t8[e] = __float2bfloat16(epi[w][lane][g*8+e]);
                        *(uint4*)(&L[ga][gc + g*8]) = *(uint4*)t8;
                    }
                }
                __syncwarp();
            }
        __syncthreads();
    }
    #undef F1_STAGE

    // ---- split softmax over 128 cols: row = tid>>2, 4 threads/row ----
    {
        int row = tid >> 2, q = tid & 3;
        float m = -1e30f;
        #pragma unroll 8
        for (int c = 0; c < 32; c++)
            m = fmaxf(m, __bfloat162float(L[row][q*32 + c]));
        m = fmaxf(m, __shfl_xor_sync(0xffffffffu, m, 1));
        m = fmaxf(m, __shfl_xor_sync(0xffffffffu, m, 2));
        float sum = 0.f;
        #pragma unroll 8
        for (int c = 0; c < 32; c++) {
            float p = __expf(__bfloat162float(L[row][q*32 + c]) - m);
            sum += p;
            L[row][q*32 + c] = __float2bfloat16(p);
        }
        sum += __shfl_xor_sync(0xffffffffu, sum, 1);
        sum += __shfl_xor_sync(0xffffffffu, sum, 2);
        if (q == 0)
            g_stats[(b*SPL + split)*NA + row] = make_float2(m, sum);
    }
    __syncthreads();

    // ---- pass 2: u_split[64,256] = P[64,128] @ x_split[128,256] (bf16 out) ----
    {
        wmma::fragment<wmma::accumulator,16,16,16,float> acc[2][4];
        #pragma unroll
        for (int i = 0; i < 2; i++)
            #pragma unroll
            for (int j = 0; j < 4; j++) wmma::fill_fragment(acc[i][j], 0.f);

        #define F2_STAGE(kc, bb) {                                                 \
            _Pragma("unroll")                                                      \
            for (int r = 0; r < 4; r++) {                                          \
                int idx = tid + r*256;                                             \
                int vr = idx >> 5, vc = (idx & 31) * 8;                            \
                CPA16(sV + (uint32_t)(bb)*16896u + (uint32_t)vr*528u + (uint32_t)vc*2u,\
                      g_xb + (size_t)(b*NT + tok0 + (kc) + vr)*DD + vc);           \
            }                                                                      \
            CPA_COMMIT(); }

        F2_STAGE(0, 0);
        for (int s = 0; s < 4; s++) {
            CPA_WAIT(0);
            __syncthreads();
            if (s < 3) F2_STAGE((s+1)*32, (s+1)&1);
            int bb = s & 1;
            #pragma unroll
            for (int kk = 0; kk < 2; kk++) {
                wmma::fragment<wmma::matrix_a,16,16,16,__nv_bfloat16,wmma::row_major> af[2];
                wmma::fragment<wmma::matrix_b,16,16,16,__nv_bfloat16,wmma::row_major> bf[4];
                #pragma unroll
                for (int i = 0; i < 2; i++)
                    wmma::load_matrix_sync(af[i], &L[wm*32 + i*16][s*32 + kk*16], 136);
                #pragma unroll
                for (int j = 0; j < 4; j++)
                    wmma::load_matrix_sync(bf[j], &Vs[bb][kk*16][wn*64 + j*16], 264);
                #pragma unroll
                for (int i = 0; i < 2; i++)
                    #pragma unroll
                    for (int j = 0; j < 4; j++)
                        wmma::mma_sync(acc[i][j], af[i], bf[j], acc[i][j]);
            }
        }
        #undef F2_STAGE
        __syncthreads();

        __nv_bfloat16* outb = g_vapb + (size_t)(b*SPL + split)*NA*DD;
        #pragma unroll
        for (int i = 0; i < 2; i++)
            #pragma unroll
            for (int j = 0; j < 4; j++) {
                wmma::store_matrix_sync(&epi[w][0][0], acc[i][j], 16, wmma::mem_row_major);
                __syncwarp();
                #pragma unroll
                for (int e = 0; e < 2; e++) {
                    int idx2 = lane + e*32;
                    int r = idx2 >> 2, c4 = (idx2 & 3) * 4;
                    int ga = wm*32 + i*16 + r;
                    int gd = wn*64 + j*16 + c4;
                    __nv_bfloat16 t4[4];
                    #pragma unroll
                    for (int e2 = 0; e2 < 4; e2++)
                        t4[e2] = __float2bfloat16(epi[w][r][c4+e2]);
                    *(uint2*)(outb + (size_t)ga*DD + gd) = *(uint2*)t4;
                }
                __syncwarp();
            }
    }
}

// ---------------- fc1: combine splits (rescale), then va2 = u @ Wvf2 + bvf2 --
__global__ void fc1k() {
    __shared__ float r0[DD];
    __shared__ float ms[SPL], ss[SPL];
    int row = blockIdx.x;  // b*NA + a
    int b = row >> 6, a = row & 63;
    int i = threadIdx.x;

    if (i < SPL) {
        float2 st = g_stats[(b*SPL + i)*NA + a];
        ms[i] = st.x; ss[i] = st.y;
    }
    __syncthreads();
    float m = -1e30f;
    #pragma unroll
    for (int s = 0; s < SPL; s++) m = fmaxf(m, ms[s]);
    float S = 0.f;
    float wsc[SPL];
    #pragma unroll
    for (int s = 0; s < SPL; s++) {
        wsc[s] = __expf(ms[s] - m);
        S += wsc[s] * ss[s];
    }
    float acc = 0.f;
    #pragma unroll
    for (int s = 0; s < SPL; s++)
        acc += wsc[s] * __bfloat162float(g_vapb[(size_t)(b*SPL + s)*NA*DD + (size_t)a*DD + i]);
    r0[i] = acc / S;
    __syncthreads();
    int o = threadIdx.x;
    float sum = g_bvf2[o];
    #pragma unroll 8
    for (int d = 0; d < DD; d++) sum += r0[d] * g_Wvf2[d*DD + o];
    g_va[(size_t)row*DD + o] = __float2bfloat16(sum);
}

// ======== stage 2 (64-token tiles): logits -> softmax -> P@va2 + bfc2 + x ====
__global__ void __launch_bounds__(256) stage2(const float* __restrict__ bfc2,
                                              const float* __restrict__ x,
                                              float* __restrict__ out) {
    extern __shared__ __align__(16) char sm2[];
    __nv_bfloat16 (*Qs)[64][40] = ( __nv_bfloat16(*)[64][40]) sm2;
    __nv_bfloat16 (*Ka)[64][40] = ( __nv_bfloat16(*)[64][40]) (sm2 + 10240);
    float* logits               = ( float*)                   (sm2 + 20480);
    __nv_bfloat16 (*Vs)[264]    = ( __nv_bfloat16(*)[264])    (sm2 + 37888);
    __nv_bfloat16 (*Pm)[72]     = ( __nv_bfloat16(*)[72])     sm2;
    float (*epi)[16][16]        = ( float(*)[16][16])         (sm2 + 10240);
    __shared__ float dbs[NA];
    uint32_t sQ = smem_u32(sm2), sKa = sQ + 10240u, sV = sQ + 37888u;

    int b = blockIdx.y, t0 = blockIdx.x * 64;
    int tid = threadIdx.x;
    int w = tid >> 5, lane = tid & 31;
    int wm = w >> 2, wn = w & 3;

    if (tid < NA) dbs[tid] = g_dbias[tid];

    #pragma unroll
    for (int r = 0; r < 8; r++) {
        int idx = tid + r*256;
        int vr = idx >> 5, vc = (idx & 31) * 8;
        CPA16(sV + (uint32_t)vr*528u + (uint32_t)vc*2u,
              g_va + (size_t)(b*NA + vr)*DD + vc);
    }
    CPA_COMMIT();

    // --- phase A: logits[64,64] = x_tile[64,256] @ Ka'[64,256]^T ---
    {
        wmma::fragment<wmma::accumulator,16,16,16,float> acc[2];
        #pragma unroll
        for (int i = 0; i < 2; i++) wmma::fill_fragment(acc[i], 0.f);

        #define S2_STAGE(kc, bb) {                                                 \
            {   int qr = tid >> 2, qc = (tid & 3) * 8;                             \
                CPA16(sQ + (uint32_t)(bb)*5120u + (uint32_t)qr*80u + (uint32_t)qc*2u, \
                      g_xb + (size_t)(b*NT + t0 + qr)*DD + (kc) + qc); }           \
            {   int ar = tid >> 2, ac = (tid & 3) * 8;                             \
                CPA16(sKa + (uint32_t)(bb)*5120u + (uint32_t)ar*80u + (uint32_t)ac*2u, \
                      g_kat + (size_t)ar*DD + (kc) + ac); }                        \
            CPA_COMMIT(); }

        S2_STAGE(0, 0);
        for (int s = 0; s < 8; s++) {
            CPA_WAIT(0);
            __syncthreads();
            if (s < 7) S2_STAGE((s+1)*32, (s+1)&1);
            int bb = s & 1;
            #pragma unroll
            for (int kk = 0; kk < 2; kk++) {
                wmma::fragment<wmma::matrix_a,16,16,16,__nv_bfloat16,wmma::row_major> af[2];
                wmma::fragment<wmma::matrix_b,16,16,16,__nv_bfloat16,wmma::col_major> bf;
                #pragma unroll
                for (int i = 0; i < 2; i++)
                    wmma::load_matrix_sync(af[i], &Qs[bb][wm*32 + i*16][kk*16], 40);
                wmma::load_matrix_sync(bf, &Ka[bb][wn*16][kk*16], 40);
                #pragma unroll
                for (int i = 0; i < 2; i++)
                    wmma::mma_sync(acc[i], af[i], bf, acc[i]);
            }
        }
        #undef S2_STAGE
        __syncthreads();
        #pragma unroll
        for (int i = 0; i < 2; i++)
            wmma::store_matrix_sync(logits + (wm*32 + i*16)*68 + wn*16,
                                    acc[i], 68, wmma::mem_row_major);
    }
    __syncthreads();

    // --- phase B: per-row softmax over 64 agents (+dbias); 4 threads/row ---
    {
        int row = tid >> 2, q = tid & 3;
        const float* lr = logits + row*68 + q*16;
        float lv[16];
        #pragma unroll
        for (int c = 0; c < 16; c++) lv[c] = lr[c] + dbs[q*16 + c];
        float m = -1e30f;
        #pragma unroll
        for (int c = 0; c < 16; c++) m = fmaxf(m, lv[c]);
        m = fmaxf(m, __shfl_xor_sync(0xffffffffu, m, 1));
        m = fmaxf(m, __shfl_xor_sync(0xffffffffu, m, 2));
        float sum = 0.f;
        float pv[16];
        #pragma unroll
        for (int c = 0; c < 16; c++) { pv[c] = __expf(lv[c] - m); sum += pv[c]; }
        sum += __shfl_xor_sync(0xffffffffu, sum, 1);
        sum += __shfl_xor_sync(0xffffffffu, sum, 2);
        float inv = 1.f / sum;
        __syncthreads();
        #pragma unroll
        for (int c = 0; c < 16; c++)
            Pm[row][q*16 + c] = __float2bfloat16(pv[c] * inv);
    }
    __syncthreads();

    // --- phase C: out[64,256] = Pm[64,64] @ Vs[64,256] + bfc2 + x ---
    {
        wmma::fragment<wmma::accumulator,16,16,16,float> acc[2][4];
        #pragma unroll
        for (int i = 0; i < 2; i++)
            #pragma unroll
            for (int j = 0; j < 4; j++) wmma::fill_fragment(acc[i][j], 0.f);
        #pragma unroll
        for (int kk = 0; kk < 4; kk++) {
            wmma::fragment<wmma::matrix_a,16,16,16,__nv_bfloat16,wmma::row_major> af[2];
            wmma::fragment<wmma::matrix_b,16,16,16,__nv_bfloat16,wmma::row_major> bf[4];
            #pragma unroll
            for (int i = 0; i < 2; i++)
                wmma::load_matrix_sync(af[i], &Pm[wm*32 + i*16][kk*16], 72);
            #pragma unroll
            for (int j = 0; j < 4; j++)
                wmma::load_matrix_sync(bf[j], &Vs[kk*16][wn*64 + j*16], 264);
            #pragma unroll
            for (int i = 0; i < 2; i++)
                #pragma unroll
                for (int j = 0; j < 4; j++)
                    wmma::mma_sync(acc[i][j], af[i], bf[j], acc[i][j]);
        }
        __syncthreads();
        int r = lane >> 1, c8 = (lane & 1) * 8;
        #pragma unroll
        for (int i = 0; i < 2; i++)
            #pragma unroll
            for (int j = 0; j < 4; j++) {
                wmma::store_matrix_sync(&epi[w][0][0], acc[i][j], 16, wmma::mem_row_major);
                __syncwarp();
                int grow = t0 + wm*32 + i*16 + r;
                int gcol = wn*64 + j*16 + c8;
                size_t gi = (size_t)(b*NT + grow)*DD + gcol;
                float o0[4], o1[4];
                #pragma unroll
                for (int e = 0; e < 4; e++)
                    o0[e] = epi[w][r][c8+e]   + bfc2[gcol+e]   + x[gi+e];
                #pragma unroll
                for (int e = 0; e < 4; e++)
                    o1[e] = epi[w][r][c8+4+e] + bfc2[gcol+4+e] + x[gi+4+e];
                *(float4*)(out + gi)     = *(float4*)o0;
                *(float4*)(out + gi + 4) = *(float4*)o1;
                __syncwarp();
            }
    }
}

// ---------------- launcher ---------------------------------------------------
#define S1F_SMEM 59392
#define S2_SMEM  71680
#define PREP_SMEM 45056

extern "C" void kernel_launch(void* const* d_in, const int* in_sizes, int n_in,
                              void* d_out, int out_size) {
    const float* agent = (const float*)d_in[0];
    const float* x     = (const float*)d_in[1];
    const float* Wqkv  = (const float*)d_in[2];
    const float* bqkv  = (const float*)d_in[3];
    const float* Wag   = (const float*)d_in[4];
    const float* bag   = (const float*)d_in[5];
    const float* Wfc1  = (const float*)d_in[6];
    const float* bfc1  = (const float*)d_in[7];
    const float* Wfc2  = (const float*)d_in[8];
    const float* bfc2  = (const float*)d_in[9];
    float* out = (float*)d_out;

    cudaFuncSetAttribute(s1fused, cudaFuncAttributeMaxDynamicSharedMemorySize, S1F_SMEM);
    cudaFuncSetAttribute(stage2,  cudaFuncAttributeMaxDynamicSharedMemorySize, S2_SMEM);
    cudaFuncSetAttribute(prep0,   cudaFuncAttributeMaxDynamicSharedMemorySize, PREP_SMEM);

    prep0<<<1104, 512, PREP_SMEM>>>(x, Wqkv, Wfc1, Wfc2, agent, Wag, bag);
    prep1<<<89, 256, PREP_SMEM>>>(bqkv, Wfc1, bfc1, Wfc2);
    s1fused<<<dim3(SPL, NB), 256, S1F_SMEM>>>();
    fc1k<<<512, 256>>>();
    stage2<<<dim3(64, 8), 256, S2_SMEM>>>(bfc2, x, out);
}

// round 14
// speedup vs baseline: 1.0850x; 1.0354x over previous
#include <cuda_runtime.h>
#include <cuda_bf16.h>
#include <mma.h>
#include <cstdint>

using namespace nvcuda;

#define NB 8
#define NT 4096
#define NA 64
#define DD 256
#define MTOK (NB*NT)
#define W3 (3*DD)
#define SPL 32
#define TSPL 128   // tokens per split

// ---------------- scratch (device globals; no allocations allowed) ----------
__device__ __nv_bfloat16 g_xb[MTOK*DD];              // x in bf16
__device__ __nv_bfloat16 g_Wqkvb[DD*W3];             // W_qkv bf16 [K, 3N]
__device__ __nv_bfloat16 g_Wffb[DD*DD];              // Wfc1@Wfc2 bf16
__device__ __nv_bfloat16 g_qasb[NA*DD];              // qa_s bf16 (scale folded)
__device__ __nv_bfloat16 g_kasb[NA*DD];              // ka_s bf16 (scale folded)
__device__ float        g_kaf[NA*DD];                // ka_s fp32 (for dbias)
__device__ __nv_bfloat16 g_qap[NA*DD];               // qa' = qa_s @ Wk^T, bf16
__device__ __nv_bfloat16 g_kat[NA*DD];               // Ka' [a,i] bf16
__device__ float        g_dbias[NA];                 // bq . ka_s
__device__ __nv_bfloat16 g_Wvf2b[DD*DD];             // Wv@(Wfc1@Wfc2), bf16
__device__ float        g_bvf2[DD];                  // (bv@Wfc1+bfc1)@Wfc2
__device__ __nv_bfloat16 g_vapb[NB*SPL*NA*DD];       // unnormalized split partials (bf16)
__device__ float2       g_stats[NB*SPL*NA];          // (m_s, s_s) per split-row
__device__ __nv_bfloat16 g_ub[NB*NA*DD];             // combined u, bf16
__device__ __nv_bfloat16 g_va[NB*NA*DD];             // va2 bf16

// ---------------- cp.async helpers ------------------------------------------
__device__ __forceinline__ uint32_t smem_u32(const void* p) {
    uint32_t a;
    asm("{ .reg .u64 t; cvta.to.shared.u64 t, %1; cvt.u32.u64 %0, t; }" : "=r"(a) : "l"(p));
    return a;
}
#define CPA16(s, g)  asm volatile("cp.async.cg.shared.global [%0], [%1], 16;" :: "r"(s), "l"(g))
#define CPA_COMMIT() asm volatile("cp.async.commit_group;" ::: "memory")
#define CPA_WAIT(n)  asm volatile("cp.async.wait_group %0;" :: "n"(n) : "memory")

// ---------------- device: Wff tile = Wfc1@Wfc2 (fp32 src, 512 threads) -------
__device__ void dev_wff(char* sm, int bx, int by,
                        const float* __restrict__ A, const float* __restrict__ B) {
    __nv_bfloat16 (*As)[72] = (__nv_bfloat16(*)[72]) sm;
    __nv_bfloat16 (*Bs)[72] = (__nv_bfloat16(*)[72])(sm + 9216);
    float (*epi)[16][16]    = (float(*)[16][16])    (sm + 18432);
    int row0 = by*64, col0 = bx*64;
    int tid = threadIdx.x, w = tid >> 5, lane = tid & 31;
    int wm = w >> 2, wn = w & 3;   // valid for w < 8

    wmma::fragment<wmma::accumulator,16,16,16,float> acc[2];
    #pragma unroll
    for (int i = 0; i < 2; i++) wmma::fill_fragment(acc[i], 0.f);

    for (int kc = 0; kc < 4; kc++) {
        #pragma unroll
        for (int r = 0; r < 2; r++) {
            int idx = tid + r*512;
            int ar = idx >> 4, ac = (idx & 15) * 4;
            float4 va4 = *(const float4*)(A + (size_t)(row0+ar)*DD + kc*64 + ac);
            __nv_bfloat16 ta[4] = {__float2bfloat16(va4.x), __float2bfloat16(va4.y),
                                   __float2bfloat16(va4.z), __float2bfloat16(va4.w)};
            *(uint2*)(&As[ar][ac]) = *(uint2*)ta;
            float4 vb4 = *(const float4*)(B + (size_t)(kc*64+ar)*DD + col0 + ac);
            __nv_bfloat16 tb[4] = {__float2bfloat16(vb4.x), __float2bfloat16(vb4.y),
                                   __float2bfloat16(vb4.z), __float2bfloat16(vb4.w)};
            *(uint2*)(&Bs[ar][ac]) = *(uint2*)tb;
        }
        __syncthreads();
        if (w < 8) {
            #pragma unroll
            for (int k4 = 0; k4 < 4; k4++) {
                wmma::fragment<wmma::matrix_a,16,16,16,__nv_bfloat16,wmma::row_major> af[2];
                wmma::fragment<wmma::matrix_b,16,16,16,__nv_bfloat16,wmma::row_major> bf;
                #pragma unroll
                for (int i = 0; i < 2; i++)
                    wmma::load_matrix_sync(af[i], &As[wm*32 + i*16][k4*16], 72);
                wmma::load_matrix_sync(bf, &Bs[k4*16][wn*16], 72);
                #pragma unroll
                for (int i = 0; i < 2; i++)
                    wmma::mma_sync(acc[i], af[i], bf, acc[i]);
            }
        }
        __syncthreads();
    }
    if (w < 8) {
        int r = lane >> 1, c8 = (lane & 1) * 8;
        #pragma unroll
        for (int i = 0; i < 2; i++) {
            wmma::store_matrix_sync(&epi[w][0][0], acc[i], 16, wmma::mem_row_major);
            __syncwarp();
            int gr = row0 + wm*32 + i*16 + r;
            int gc = col0 + wn*16 + c8;
            __nv_bfloat16 t8[8];
            #pragma unroll
            for (int e = 0; e < 8; e++)
                t8[e] = __float2bfloat16(epi[w][r][c8+e]);
            *(uint4*)(g_Wffb + (size_t)gr*DD + gc) = *(uint4*)t8;
            __syncwarp();
        }
    }
}

// ================= prep0: conv(x, Wqkv) || agent_proj || Wff ================
__global__ void __launch_bounds__(512) prep0(const float* __restrict__ x,
                                             const float* __restrict__ Wqkv,
                                             const float* __restrict__ Wfc1,
                                             const float* __restrict__ Wfc2,
                                             const float* __restrict__ agent,
                                             const float* __restrict__ Wag,
                                             const float* __restrict__ bag) {
    extern __shared__ __align__(16) char smp[];
    if (blockIdx.x < 1024) {
        int tid = blockIdx.x * 512 + threadIdx.x;
        int stride = 1024 * 512;
        for (int i = tid; i < (MTOK*DD)/4; i += stride) {
            float4 v = *(const float4*)(x + i*4);
            __nv_bfloat16 t[4] = {__float2bfloat16(v.x), __float2bfloat16(v.y),
                                  __float2bfloat16(v.z), __float2bfloat16(v.w)};
            *(uint2*)(g_xb + i*4) = *(uint2*)t;
        }
        for (int i = tid; i < DD*W3; i += stride)
            g_Wqkvb[i] = __float2bfloat16(Wqkv[i]);
    } else if (blockIdx.x < 1088) {
        __shared__ float arow[DD];
        int a = blockIdx.x - 1024;
        for (int i = threadIdx.x; i < DD; i += 512)
            arow[i] = agent[a*DD + i];
        __syncthreads();
        int o = threadIdx.x;  // 0..511
        float s = 0.f;
        #pragma unroll 8
        for (int d = 0; d < DD; d++)
            s += arow[d] * Wag[d*2*DD + o];
        s += bag[o];
        s *= 0.0625f;  // 256^-0.5
        if (o < DD) {
            g_qasb[a*DD + o] = __float2bfloat16(s);
        } else {
            g_kasb[a*DD + (o-DD)] = __float2bfloat16(s);
            g_kaf [a*DD + (o-DD)] = s;
        }
    } else {
        int t = blockIdx.x - 1088;
        dev_wff(smp, t & 3, t >> 2, Wfc1, Wfc2);
    }
}

// ---------------- device: proj_agents tile (256 thr) -------------------------
__device__ void dev_proj_agents(char* sm, int ix, int sel) {
    __nv_bfloat16 (*Aa)[64][40] = (__nv_bfloat16(*)[64][40]) sm;
    __nv_bfloat16 (*Ws)[64][40] = (__nv_bfloat16(*)[64][40])(sm + 10240);
    float (*epi)[16][16]        = (float(*)[16][16])        (sm + 20480);
    uint32_t sA = smem_u32(sm), sW = sA + 10240u;

    int col0 = ix * 64;
    const __nv_bfloat16* A  = sel ? g_kasb : g_qasb;
    const __nv_bfloat16* Bb = g_Wqkvb + (sel ? 0 : DD);
    __nv_bfloat16* C = sel ? g_kat : g_qap;
    int tid = threadIdx.x;
    int w = tid >> 5, lane = tid & 31;
    int wm = w >> 2, wn = w & 3;

    wmma::fragment<wmma::accumulator,16,16,16,float> acc[2];
    #pragma unroll
    for (int i = 0; i < 2; i++) wmma::fill_fragment(acc[i], 0.f);

    #define PA_STAGE(kc, bb) {                                                     \
        {   int ar = tid >> 2, ac = (tid & 3) * 8;                                 \
            CPA16(sA + (uint32_t)(bb)*5120u + (uint32_t)ar*80u + (uint32_t)ac*2u,  \
                  A + (size_t)ar*DD + (kc) + ac); }                                \
        {   int wr = tid >> 2, wc = (tid & 3) * 8;                                 \
            CPA16(sW + (uint32_t)(bb)*5120u + (uint32_t)wr*80u + (uint32_t)wc*2u,  \
                  Bb + (size_t)(col0 + wr)*W3 + (kc) + wc); }                      \
        CPA_COMMIT(); }

    PA_STAGE(0, 0);
    for (int s = 0; s < 8; s++) {
        CPA_WAIT(0);
        __syncthreads();
        if (s < 7) PA_STAGE((s+1)*32, (s+1)&1);
        int bb = s & 1;
        #pragma unroll
        for (int kk = 0; kk < 2; kk++) {
            wmma::fragment<wmma::matrix_a,16,16,16,__nv_bfloat16,wmma::row_major> af[2];
            wmma::fragment<wmma::matrix_b,16,16,16,__nv_bfloat16,wmma::col_major> bf;
            #pragma unroll
            for (int i = 0; i < 2; i++)
                wmma::load_matrix_sync(af[i], &Aa[bb][wm*32 + i*16][kk*16], 40);
            wmma::load_matrix_sync(bf, &Ws[bb][wn*16][kk*16], 40);
            #pragma unroll
            for (int i = 0; i < 2; i++)
                wmma::mma_sync(acc[i], af[i], bf, acc[i]);
        }
    }
    #undef PA_STAGE

    #pragma unroll
    for (int i = 0; i < 2; i++) {
        wmma::store_matrix_sync(&epi[w][0][0], acc[i], 16, wmma::mem_row_major);
        __syncwarp();
        if (lane < 16) {
            int a = wm*32 + i*16 + lane;
            __nv_bfloat16 t8[8];
            #pragma unroll
            for (int g = 0; g < 2; g++) {
                #pragma unroll
                for (int e = 0; e < 8; e++)
                    t8[e] = __float2bfloat16(epi[w][lane][g*8+e]);
                *(uint4*)(C + (size_t)a*DD + col0 + wn*16 + g*8) = *(uint4*)t8;
            }
        }
        __syncwarp();
    }
}

// ---------------- device: Wvf2 tile = Wv @ Wffb (cp.async, bf16 out) ---------
__device__ void dev_wvf2(char* sm, int bx, int by) {
    __nv_bfloat16 (*As)[64][72] = (__nv_bfloat16(*)[64][72]) sm;
    __nv_bfloat16 (*Bs)[64][72] = (__nv_bfloat16(*)[64][72])(sm + 18432);
    float (*epi)[16][16]        = (float(*)[16][16])        (sm + 36864);
    uint32_t sA = smem_u32(sm), sB = sA + 18432u;

    int row0 = by * 64, col0 = bx * 64;
    const __nv_bfloat16* A = g_Wqkvb + 2*DD;   // Wv rows, lda = W3
    const __nv_bfloat16* B = g_Wffb;           // lda = DD
    int tid = threadIdx.x, w = tid >> 5, lane = tid & 31;
    int wm = w >> 2, wn = w & 3;

    wmma::fragment<wmma::accumulator,16,16,16,float> acc[2];
    #pragma unroll
    for (int i = 0; i < 2; i++) wmma::fill_fragment(acc[i], 0.f);

    #define WV_STAGE(kc, bb) {                                                     \
        _Pragma("unroll")                                                          \
        for (int r = 0; r < 2; r++) {                                              \
            int idx = tid + r*256;                                                 \
            int ar = idx >> 3, ac = (idx & 7) * 8;                                 \
            CPA16(sA + (uint32_t)(bb)*9216u + (uint32_t)ar*144u + (uint32_t)ac*2u, \
                  A + (size_t)(row0+ar)*W3 + (kc) + ac);                           \
        }                                                                          \
        _Pragma("unroll")                                                          \
        for (int r = 0; r < 2; r++) {                                              \
            int idx = tid + r*256;                                                 \
            int br = idx >> 3, bc = (idx & 7) * 8;                                 \
            CPA16(sB + (uint32_t)(bb)*9216u + (uint32_t)br*144u + (uint32_t)bc*2u, \
                  B + (size_t)((kc)+br)*DD + col0 + bc);                           \
        }                                                                          \
        CPA_COMMIT(); }

    WV_STAGE(0, 0);
    for (int s = 0; s < 4; s++) {
        CPA_WAIT(0);
        __syncthreads();
        if (s < 3) WV_STAGE((s+1)*64, (s+1)&1);
        int bb = s & 1;
        #pragma unroll
        for (int k4 = 0; k4 < 4; k4++) {
            wmma::fragment<wmma::matrix_a,16,16,16,__nv_bfloat16,wmma::row_major> af[2];
            wmma::fragment<wmma::matrix_b,16,16,16,__nv_bfloat16,wmma::row_major> bf;
            #pragma unroll
            for (int i = 0; i < 2; i++)
                wmma::load_matrix_sync(af[i], &As[bb][wm*32 + i*16][k4*16], 72);
            wmma::load_matrix_sync(bf, &Bs[bb][k4*16][wn*16], 72);
            #pragma unroll
            for (int i = 0; i < 2; i++)
                wmma::mma_sync(acc[i], af[i], bf, acc[i]);
        }
    }
    #undef WV_STAGE
    __syncthreads();

    int r = lane >> 1, c8 = (lane & 1) * 8;
    #pragma unroll
    for (int i = 0; i < 2; i++) {
        wmma::store_matrix_sync(&epi[w][0][0], acc[i], 16, wmma::mem_row_major);
        __syncwarp();
        int gr = row0 + wm*32 + i*16 + r;
        int gc = col0 + wn*16 + c8;
        __nv_bfloat16 t8[8];
        #pragma unroll
        for (int e = 0; e < 8; e++)
            t8[e] = __float2bfloat16(epi[w][r][c8+e]);
        *(uint4*)(g_Wvf2b + (size_t)gr*DD + gc) = *(uint4*)t8;
        __syncwarp();
    }
}

// ===== prep1: proj_agents || Wvf2 || dbias || bvf2 (grid 89, 256 thr) ========
__global__ void __launch_bounds__(256) prep1(const float* __restrict__ bqkv,
                                             const float* __restrict__ Wfc1,
                                             const float* __restrict__ bfc1,
                                             const float* __restrict__ Wfc2) {
    extern __shared__ __align__(16) char sm[];
    int bid = blockIdx.x;
    if (bid < 8) {
        dev_proj_agents(sm, bid & 3, bid >> 2);
    } else if (bid < 24) {
        int t = bid - 8;
        dev_wvf2(sm, t & 3, t >> 2);
    } else if (bid < 88) {
        float* red = (float*)sm;
        int a = bid - 24, i = threadIdx.x;
        red[i] = bqkv[i] * g_kaf[a*DD + i];
        __syncthreads();
        for (int st = 128; st > 0; st >>= 1) {
            if (i < st) red[i] += red[i + st];
            __syncthreads();
        }
        if (i == 0) g_dbias[a] = red[0];
    } else {
        // bvf2 = (bv@Wfc1 + bfc1) @ Wfc2, two chained GEMVs
        float* bvf = (float*)sm;
        int j = threadIdx.x;
        float t = bfc1[j];
        #pragma unroll 8
        for (int o = 0; o < DD; o++)
            t += bqkv[2*DD + o] * Wfc1[o*DD + j];
        bvf[j] = t;
        __syncthreads();
        float t2 = 0.f;
        #pragma unroll 8
        for (int o = 0; o < DD; o++)
            t2 += bvf[o] * Wfc2[o*DD + j];
        g_bvf2[j] = t2;
    }
}

// ======== fused stage-1 (SPL=32): logits[64,128] -> softmax -> u[64,256] ====
__global__ void __launch_bounds__(256) s1fused() {
    extern __shared__ __align__(16) char smf[];
    __nv_bfloat16 (*L)[136]      = ( __nv_bfloat16(*)[136]) smf;
    __nv_bfloat16 (*Qa)[64][40]  = ( __nv_bfloat16(*)[64][40]) (smf + 17408);
    __nv_bfloat16 (*Ks)[128][40] = ( __nv_bfloat16(*)[128][40])(smf + 27648);
    __nv_bfloat16 (*Vs)[32][264] = ( __nv_bfloat16(*)[32][264])(smf + 17408);
    float (*epi)[16][16]         = ( float(*)[16][16])         (smf + 51200);
    uint32_t sQ = smem_u32(smf) + 17408u;
    uint32_t sK = smem_u32(smf) + 27648u;
    uint32_t sV = smem_u32(smf) + 17408u;

    int split = blockIdx.x, b = blockIdx.y;
    int tok0 = split * TSPL;
    int tid = threadIdx.x;
    int w = tid >> 5, lane = tid & 31;
    int wm = w >> 2, wn = w & 3;

    // ---- pass 1: logits[64,128] ----
    #define F1_STAGE(kc, bb) {                                                     \
        {   int ar = tid >> 2, ac = (tid & 3) * 8;                                 \
            CPA16(sQ + (uint32_t)(bb)*5120u + (uint32_t)ar*80u + (uint32_t)ac*2u,  \
                  g_qap + (size_t)ar*DD + (kc) + ac); }                            \
        _Pragma("unroll")                                                          \
        for (int r = 0; r < 2; r++) {                                              \
            int idx = tid + r*256;                                                 \
            int kr = idx >> 2, kcc = (idx & 3) * 8;                                \
            CPA16(sK + (uint32_t)(bb)*10240u + (uint32_t)kr*80u + (uint32_t)kcc*2u,\
                  g_xb + (size_t)(b*NT + tok0 + kr)*DD + (kc) + kcc);              \
        }                                                                          \
        CPA_COMMIT(); }

    {
        wmma::fragment<wmma::accumulator,16,16,16,float> acc[2][2];
        #pragma unroll
        for (int i = 0; i < 2; i++)
            #pragma unroll
            for (int j = 0; j < 2; j++) wmma::fill_fragment(acc[i][j], 0.f);

        F1_STAGE(0, 0);
        for (int s = 0; s < 8; s++) {
            CPA_WAIT(0);
            __syncthreads();
            if (s < 7) F1_STAGE((s+1)*32, (s+1)&1);
            int bb = s & 1;
            #pragma unroll
            for (int kk = 0; kk < 2; kk++) {
                wmma::fragment<wmma::matrix_a,16,16,16,__nv_bfloat16,wmma::row_major> af[2];
                wmma::fragment<wmma::matrix_b,16,16,16,__nv_bfloat16,wmma::col_major> bf[2];
                #pragma unroll
                for (int i = 0; i < 2; i++)
                    wmma::load_matrix_sync(af[i], &Qa[bb][wm*32 + i*16][kk*16], 40);
                #pragma unroll
                for (int j = 0; j < 2; j++)
                    wmma::load_matrix_sync(bf[j], &Ks[bb][wn*32 + j*16][kk*16], 40);
                #pragma unroll
                for (int i = 0; i < 2; i++)
                    #pragma unroll
                    for (int j = 0; j < 2; j++)
                        wmma::mma_sync(acc[i][j], af[i], bf[j], acc[i][j]);
            }
        }
        __syncthreads();
        #pragma unroll
        for (int i = 0; i < 2; i++)
            #pragma unroll
            for (int j = 0; j < 2; j++) {
                wmma::store_matrix_sync(&epi[w][0][0], acc[i][j], 16, wmma::mem_row_major);
                __syncwarp();
                if (lane < 16) {
                    int ga = wm*32 + i*16 + lane;
                    int gc = wn*32 + j*16;
                    __nv_bfloat16 t8[8];
                    #pragma unroll
                    for (int g = 0; g < 2; g++) {
                        #pragma unroll
                        for (int e = 0; e < 8; e++)
                            t8[e] = __float2bfloat16(epi[w][lane][g*8+e]);
                        *(uint4*)(&L[ga][gc + g*8]) = *(uint4*)t8;
                    }
                }
                __syncwarp();
            }
        __syncthreads();
    }
    #undef F1_STAGE

    // ---- split softmax over 128 cols: row = tid>>2, 4 threads/row ----
    {
        int row = tid >> 2, q = tid & 3;
        float m = -1e30f;
        #pragma unroll 8
        for (int c = 0; c < 32; c++)
            m = fmaxf(m, __bfloat162float(L[row][q*32 + c]));
        m = fmaxf(m, __shfl_xor_sync(0xffffffffu, m, 1));
        m = fmaxf(m, __shfl_xor_sync(0xffffffffu, m, 2));
        float sum = 0.f;
        #pragma unroll 8
        for (int c = 0; c < 32; c++) {
            float p = __expf(__bfloat162float(L[row][q*32 + c]) - m);
            sum += p;
            L[row][q*32 + c] = __float2bfloat16(p);
        }
        sum += __shfl_xor_sync(0xffffffffu, sum, 1);
        sum += __shfl_xor_sync(0xffffffffu, sum, 2);
        if (q == 0)
            g_stats[(b*SPL + split)*NA + row] = make_float2(m, sum);
    }
    __syncthreads();

    // ---- pass 2: u_split[64,256] = P[64,128] @ x_split[128,256] (bf16 out) ----
    {
        wmma::fragment<wmma::accumulator,16,16,16,float> acc[2][4];
        #pragma unroll
        for (int i = 0; i < 2; i++)
            #pragma unroll
            for (int j = 0; j < 4; j++) wmma::fill_fragment(acc[i][j], 0.f);

        #define F2_STAGE(kc, bb) {                                                 \
            _Pragma("unroll")                                                      \
            for (int r = 0; r < 4; r++) {                                          \
                int idx = tid + r*256;                                             \
                int vr = idx >> 5, vc = (idx & 31) * 8;                            \
                CPA16(sV + (uint32_t)(bb)*16896u + (uint32_t)vr*528u + (uint32_t)vc*2u,\
                      g_xb + (size_t)(b*NT + tok0 + (kc) + vr)*DD + vc);           \
            }                                                                      \
            CPA_COMMIT(); }

        F2_STAGE(0, 0);
        for (int s = 0; s < 4; s++) {
            CPA_WAIT(0);
            __syncthreads();
            if (s < 3) F2_STAGE((s+1)*32, (s+1)&1);
            int bb = s & 1;
            #pragma unroll
            for (int kk = 0; kk < 2; kk++) {
                wmma::fragment<wmma::matrix_a,16,16,16,__nv_bfloat16,wmma::row_major> af[2];
                wmma::fragment<wmma::matrix_b,16,16,16,__nv_bfloat16,wmma::row_major> bf[4];
                #pragma unroll
                for (int i = 0; i < 2; i++)
                    wmma::load_matrix_sync(af[i], &L[wm*32 + i*16][s*32 + kk*16], 136);
                #pragma unroll
                for (int j = 0; j < 4; j++)
                    wmma::load_matrix_sync(bf[j], &Vs[bb][kk*16][wn*64 + j*16], 264);
                #pragma unroll
                for (int i = 0; i < 2; i++)
                    #pragma unroll
                    for (int j = 0; j < 4; j++)
                        wmma::mma_sync(acc[i][j], af[i], bf[j], acc[i][j]);
            }
        }
        #undef F2_STAGE
        __syncthreads();

        __nv_bfloat16* outb = g_vapb + (size_t)(b*SPL + split)*NA*DD;
        #pragma unroll
        for (int i = 0; i < 2; i++)
            #pragma unroll
            for (int j = 0; j < 4; j++) {
                wmma::store_matrix_sync(&epi[w][0][0], acc[i][j], 16, wmma::mem_row_major);
                __syncwarp();
                #pragma unroll
                for (int e = 0; e < 2; e++) {
                    int idx2 = lane + e*32;
                    int r = idx2 >> 2, c4 = (idx2 & 3) * 4;
                    int ga = wm*32 + i*16 + r;
                    int gd = wn*64 + j*16 + c4;
                    __nv_bfloat16 t4[4];
                    #pragma unroll
                    for (int e2 = 0; e2 < 4; e2++)
                        t4[e2] = __float2bfloat16(epi[w][r][c4+e2]);
                    *(uint2*)(outb + (size_t)ga*DD + gd) = *(uint2*)t4;
                }
                __syncwarp();
            }
    }
}

// ---------------- combine: log-sum-exp split merge -> u bf16 -----------------
__global__ void __launch_bounds__(256) combine_k() {
    __shared__ float ms[SPL], ss[SPL];
    int row = blockIdx.x;  // b*NA + a
    int b = row >> 6, a = row & 63;
    int i = threadIdx.x;

    if (i < SPL) {
        float2 st = g_stats[(b*SPL + i)*NA + a];
        ms[i] = st.x; ss[i] = st.y;
    }
    __syncthreads();
    float m = -1e30f;
    #pragma unroll
    for (int s = 0; s < SPL; s++) m = fmaxf(m, ms[s]);
    float S = 0.f;
    float wsc[SPL];
    #pragma unroll
    for (int s = 0; s < SPL; s++) {
        wsc[s] = __expf(ms[s] - m);
        S += wsc[s] * ss[s];
    }
    float invS = 1.f / S;
    float acc = 0.f;
    #pragma unroll
    for (int s = 0; s < SPL; s++)
        acc += wsc[s] * __bfloat162float(g_vapb[(size_t)(b*SPL + s)*NA*DD + (size_t)a*DD + i]);
    g_ub[(size_t)row*DD + i] = __float2bfloat16(acc * invS);
}

// ---------------- fc2v: va2[512,256] = u @ Wvf2b + bvf2 (WMMA) ---------------
// grid (4, 8): 64x64 tile per block; rows = b*64.., cols = bx*64..
__global__ void __launch_bounds__(256) fc2v() {
    __shared__ __nv_bfloat16 As[2][64][72];
    __shared__ __nv_bfloat16 Bs[2][64][72];
    __shared__ float epi[8][16][16];
    uint32_t sA = smem_u32(&As[0][0][0]), sB = smem_u32(&Bs[0][0][0]);

    int row0 = blockIdx.y * 64, col0 = blockIdx.x * 64;
    int tid = threadIdx.x, w = tid >> 5, lane = tid & 31;
    int wm = w >> 2, wn = w & 3;

    wmma::fragment<wmma::accumulator,16,16,16,float> acc[2];
    #pragma unroll
    for (int i = 0; i < 2; i++) wmma::fill_fragment(acc[i], 0.f);

    #define FV_STAGE(kc, bb) {                                                     \
        _Pragma("unroll")                                                          \
        for (int r = 0; r < 2; r++) {                                              \
            int idx = tid + r*256;                                                 \
            int ar = idx >> 3, ac = (idx & 7) * 8;                                 \
            CPA16(sA + (uint32_t)(bb)*9216u + (uint32_t)ar*144u + (uint32_t)ac*2u, \
                  g_ub + (size_t)(row0+ar)*DD + (kc) + ac);                        \
        }                                                                          \
        _Pragma("unroll")                                                          \
        for (int r = 0; r < 2; r++) {                                              \
            int idx = tid + r*256;                                                 \
            int br = idx >> 3, bc = (idx & 7) * 8;                                 \
            CPA16(sB + (uint32_t)(bb)*9216u + (uint32_t)br*144u + (uint32_t)bc*2u, \
                  g_Wvf2b + (size_t)((kc)+br)*DD + col0 + bc);                     \
        }                                                                          \
        CPA_COMMIT(); }

    FV_STAGE(0, 0);
    for (int s = 0; s < 4; s++) {
        CPA_WAIT(0);
        __syncthreads();
        if (s < 3) FV_STAGE((s+1)*64, (s+1)&1);
        int bb = s & 1;
        #pragma unroll
        for (int k4 = 0; k4 < 4; k4++) {
            wmma::fragment<wmma::matrix_a,16,16,16,__nv_bfloat16,wmma::row_major> af[2];
            wmma::fragment<wmma::matrix_b,16,16,16,__nv_bfloat16,wmma::row_major> bf;
            #pragma unroll
            for (int i = 0; i < 2; i++)
                wmma::load_matrix_sync(af[i], &As[bb][wm*32 + i*16][k4*16], 72);
            wmma::load_matrix_sync(bf, &Bs[bb][k4*16][wn*16], 72);
            #pragma unroll
            for (int i = 0; i < 2; i++)
                wmma::mma_sync(acc[i], af[i], bf, acc[i]);
        }
    }
    #undef FV_STAGE
    __syncthreads();

    int r = lane >> 1, c8 = (lane & 1) * 8;
    #pragma unroll
    for (int i = 0; i < 2; i++) {
        wmma::store_matrix_sync(&epi[w][0][0], acc[i], 16, wmma::mem_row_major);
        __syncwarp();
        int gr = row0 + wm*32 + i*16 + r;
        int gc = col0 + wn*16 + c8;
        __nv_bfloat16 t8[8];
        #pragma unroll
        for (int e = 0; e < 8; e++)
            t8[e] = __float2bfloat16(epi[w][r][c8+e] + g_bvf2[gc+e]);
        *(uint4*)(g_va + (size_t)gr*DD + gc) = *(uint4*)t8;
        __syncwarp();
    }
}

// ======== stage 2 (64-token tiles): logits -> softmax -> P@va2 + bfc2 + x ====
__global__ void __launch_bounds__(256) stage2(const float* __restrict__ bfc2,
                                              const float* __restrict__ x,
                                              float* __restrict__ out) {
    extern __shared__ __align__(16) char sm2[];
    __nv_bfloat16 (*Qs)[64][40] = ( __nv_bfloat16(*)[64][40]) sm2;
    __nv_bfloat16 (*Ka)[64][40] = ( __nv_bfloat16(*)[64][40]) (sm2 + 10240);
    float* logits               = ( float*)                   (sm2 + 20480);
    __nv_bfloat16 (*Vs)[264]    = ( __nv_bfloat16(*)[264])    (sm2 + 37888);
    __nv_bfloat16 (*Pm)[72]     = ( __nv_bfloat16(*)[72])     sm2;
    float (*epi)[16][16]        = ( float(*)[16][16])         (sm2 + 10240);
    __shared__ float dbs[NA];
    uint32_t sQ = smem_u32(sm2), sKa = sQ + 10240u, sV = sQ + 37888u;

    int b = blockIdx.y, t0 = blockIdx.x * 64;
    int tid = threadIdx.x;
    int w = tid >> 5, lane = tid & 31;
    int wm = w >> 2, wn = w & 3;

    if (tid < NA) dbs[tid] = g_dbias[tid];

    #pragma unroll
    for (int r = 0; r < 8; r++) {
        int idx = tid + r*256;
        int vr = idx >> 5, vc = (idx & 31) * 8;
        CPA16(sV + (uint32_t)vr*528u + (uint32_t)vc*2u,
              g_va + (size_t)(b*NA + vr)*DD + vc);
    }
    CPA_COMMIT();

    // --- phase A: logits[64,64] = x_tile[64,256] @ Ka'[64,256]^T ---
    {
        wmma::fragment<wmma::accumulator,16,16,16,float> acc[2];
        #pragma unroll
        for (int i = 0; i < 2; i++) wmma::fill_fragment(acc[i], 0.f);

        #define S2_STAGE(kc, bb) {                                                 \
            {   int qr = tid >> 2, qc = (tid & 3) * 8;                             \
                CPA16(sQ + (uint32_t)(bb)*5120u + (uint32_t)qr*80u + (uint32_t)qc*2u, \
                      g_xb + (size_t)(b*NT + t0 + qr)*DD + (kc) + qc); }           \
            {   int ar = tid >> 2, ac = (tid & 3) * 8;                             \
                CPA16(sKa + (uint32_t)(bb)*5120u + (uint32_t)ar*80u + (uint32_t)ac*2u, \
                      g_kat + (size_t)ar*DD + (kc) + ac); }                        \
            CPA_COMMIT(); }

        S2_STAGE(0, 0);
        for (int s = 0; s < 8; s++) {
            CPA_WAIT(0);
            __syncthreads();
            if (s < 7) S2_STAGE((s+1)*32, (s+1)&1);
            int bb = s & 1;
            #pragma unroll
            for (int kk = 0; kk < 2; kk++) {
                wmma::fragment<wmma::matrix_a,16,16,16,__nv_bfloat16,wmma::row_major> af[2];
                wmma::fragment<wmma::matrix_b,16,16,16,__nv_bfloat16,wmma::col_major> bf;
                #pragma unroll
                for (int i = 0; i < 2; i++)
                    wmma::load_matrix_sync(af[i], &Qs[bb][wm*32 + i*16][kk*16], 40);
                wmma::load_matrix_sync(bf, &Ka[bb][wn*16][kk*16], 40);
                #pragma unroll
                for (int i = 0; i < 2; i++)
                    wmma::mma_sync(acc[i], af[i], bf, acc[i]);
            }
        }
        #undef S2_STAGE
        __syncthreads();
        #pragma unroll
        for (int i = 0; i < 2; i++)
            wmma::store_matrix_sync(logits + (wm*32 + i*16)*68 + wn*16,
                                    acc[i], 68, wmma::mem_row_major);
    }
    __syncthreads();

    // --- phase B: per-row softmax over 64 agents (+dbias); 4 threads/row ---
    {
        int row = tid >> 2, q = tid & 3;
        const float* lr = logits + row*68 + q*16;
        float lv[16];
        #pragma unroll
        for (int c = 0; c < 16; c++) lv[c] = lr[c] + dbs[q*16 + c];
        float m = -1e30f;
        #pragma unroll
        for (int c = 0; c < 16; c++) m = fmaxf(m, lv[c]);
        m = fmaxf(m, __shfl_xor_sync(0xffffffffu, m, 1));
        m = fmaxf(m, __shfl_xor_sync(0xffffffffu, m, 2));
        float sum = 0.f;
        float pv[16];
        #pragma unroll
        for (int c = 0; c < 16; c++) { pv[c] = __expf(lv[c] - m); sum += pv[c]; }
        sum += __shfl_xor_sync(0xffffffffu, sum, 1);
        sum += __shfl_xor_sync(0xffffffffu, sum, 2);
        float inv = 1.f / sum;
        __syncthreads();
        #pragma unroll
        for (int c = 0; c < 16; c++)
            Pm[row][q*16 + c] = __float2bfloat16(pv[c] * inv);
    }
    __syncthreads();

    // --- phase C: out[64,256] = Pm[64,64] @ Vs[64,256] + bfc2 + x ---
    {
        wmma::fragment<wmma::accumulator,16,16,16,float> acc[2][4];
        #pragma unroll
        for (int i = 0; i < 2; i++)
            #pragma unroll
            for (int j = 0; j < 4; j++) wmma::fill_fragment(acc[i][j], 0.f);
        #pragma unroll
        for (int kk = 0; kk < 4; kk++) {
            wmma::fragment<wmma::matrix_a,16,16,16,__nv_bfloat16,wmma::row_major> af[2];
            wmma::fragment<wmma::matrix_b,16,16,16,__nv_bfloat16,wmma::row_major> bf[4];
            #pragma unroll
            for (int i = 0; i < 2; i++)
                wmma::load_matrix_sync(af[i], &Pm[wm*32 + i*16][kk*16], 72);
            #pragma unroll
            for (int j = 0; j < 4; j++)
                wmma::load_matrix_sync(bf[j], &Vs[kk*16][wn*64 + j*16], 264);
            #pragma unroll
            for (int i = 0; i < 2; i++)
                #pragma unroll
                for (int j = 0; j < 4; j++)
                    wmma::mma_sync(acc[i][j], af[i], bf[j], acc[i][j]);
        }
        __syncthreads();
        int r = lane >> 1, c8 = (lane & 1) * 8;
        #pragma unroll
        for (int i = 0; i < 2; i++)
            #pragma unroll
            for (int j = 0; j < 4; j++) {
                wmma::store_matrix_sync(&epi[w][0][0], acc[i][j], 16, wmma::mem_row_major);
                __syncwarp();
                int grow = t0 + wm*32 + i*16 + r;
                int gcol = wn*64 + j*16 + c8;
                size_t gi = (size_t)(b*NT + grow)*DD + gcol;
                float o0[4], o1[4];
                #pragma unroll
                for (int e = 0; e < 4; e++)
                    o0[e] = epi[w][r][c8+e]   + bfc2[gcol+e]   + x[gi+e];
                #pragma unroll
                for (int e = 0; e < 4; e++)
                    o1[e] = epi[w][r][c8+4+e] + bfc2[gcol+4+e] + x[gi+4+e];
                *(float4*)(out + gi)     = *(float4*)o0;
                *(float4*)(out + gi + 4) = *(float4*)o1;
                __syncwarp();
            }
    }
}

// ---------------- launcher ---------------------------------------------------
#define S1F_SMEM 59392
#define S2_SMEM  71680
#define PREP_SMEM 45056

extern "C" void kernel_launch(void* const* d_in, const int* in_sizes, int n_in,
                              void* d_out, int out_size) {
    const float* agent = (const float*)d_in[0];
    const float* x     = (const float*)d_in[1];
    const float* Wqkv  = (const float*)d_in[2];
    const float* bqkv  = (const float*)d_in[3];
    const float* Wag   = (const float*)d_in[4];
    const float* bag   = (const float*)d_in[5];
    const float* Wfc1  = (const float*)d_in[6];
    const float* bfc1  = (const float*)d_in[7];
    const float* Wfc2  = (const float*)d_in[8];
    const float* bfc2  = (const float*)d_in[9];
    float* out = (float*)d_out;

    cudaFuncSetAttribute(s1fused, cudaFuncAttributeMaxDynamicSharedMemorySize, S1F_SMEM);
    cudaFuncSetAttribute(stage2,  cudaFuncAttributeMaxDynamicSharedMemorySize, S2_SMEM);
    cudaFuncSetAttribute(prep0,   cudaFuncAttributeMaxDynamicSharedMemorySize, PREP_SMEM);

    prep0<<<1104, 512, PREP_SMEM>>>(x, Wqkv, Wfc1, Wfc2, agent, Wag, bag);
    prep1<<<89, 256, PREP_SMEM>>>(bqkv, Wfc1, bfc1, Wfc2);
    s1fused<<<dim3(SPL, NB), 256, S1F_SMEM>>>();
    combine_k<<<512, 256>>>();
    fc2v<<<dim3(4, 8), 256>>>();
    stage2<<<dim3(64, 8), 256, S2_SMEM>>>(bfc2, x, out);
}

// round 15
// speedup vs baseline: 1.1107x; 1.0237x over previous
#include <cuda_runtime.h>
#include <cuda_bf16.h>
#include <mma.h>
#include <cstdint>

using namespace nvcuda;

#define NB 8
#define NT 4096
#define NA 64
#define DD 256
#define MTOK (NB*NT)
#define W3 (3*DD)
#define SPL 32
#define TSPL 128   // tokens per split

// ---------------- scratch (device globals; no allocations allowed) ----------
__device__ __nv_bfloat16 g_xb[MTOK*DD];              // x in bf16
__device__ __nv_bfloat16 g_Wqkvb[DD*W3];             // W_qkv bf16 [K, 3N]
__device__ __nv_bfloat16 g_Wffb[DD*DD];              // Wfc1@Wfc2 bf16
__device__ __nv_bfloat16 g_qasb[NA*DD];              // qa_s bf16 (scale folded)
__device__ __nv_bfloat16 g_kasb[NA*DD];              // ka_s bf16 (scale folded)
__device__ float        g_kaf[NA*DD];                // ka_s fp32 (for dbias)
__device__ __nv_bfloat16 g_qap[NA*DD];               // qa' = qa_s @ Wk^T, bf16
__device__ __nv_bfloat16 g_kat[NA*DD];               // Ka' [a,i] bf16
__device__ float        g_dbias[NA];                 // bq . ka_s
__device__ __nv_bfloat16 g_Wvf2b[DD*DD];             // Wv@(Wfc1@Wfc2), bf16
__device__ float        g_bvf2[DD];                  // (bv@Wfc1+bfc1)@Wfc2
__device__ __nv_bfloat16 g_vapb[NB*SPL*NA*DD];       // unnormalized split partials (bf16)
__device__ float2       g_stats[NB*SPL*NA];          // (m_s, s_s) per split-row
__device__ __nv_bfloat16 g_ub[NB*NA*DD];             // combined u, bf16
__device__ __nv_bfloat16 g_va[NB*NA*DD];             // va2 bf16

// ---------------- cp.async helpers ------------------------------------------
__device__ __forceinline__ uint32_t smem_u32(const void* p) {
    uint32_t a;
    asm("{ .reg .u64 t; cvta.to.shared.u64 t, %1; cvt.u32.u64 %0, t; }" : "=r"(a) : "l"(p));
    return a;
}
#define CPA16(s, g)  asm volatile("cp.async.cg.shared.global [%0], [%1], 16;" :: "r"(s), "l"(g))
#define CPA_COMMIT() asm volatile("cp.async.commit_group;" ::: "memory")
#define CPA_WAIT(n)  asm volatile("cp.async.wait_group %0;" :: "n"(n) : "memory")

// ---------------- device: Wff tile = Wfc1@Wfc2 (fp32 src, 512 threads) -------
__device__ void dev_wff(char* sm, int bx, int by,
                        const float* __restrict__ A, const float* __restrict__ B) {
    __nv_bfloat16 (*As)[72] = (__nv_bfloat16(*)[72]) sm;
    __nv_bfloat16 (*Bs)[72] = (__nv_bfloat16(*)[72])(sm + 9216);
    float (*epi)[16][16]    = (float(*)[16][16])    (sm + 18432);
    int row0 = by*64, col0 = bx*64;
    int tid = threadIdx.x, w = tid >> 5, lane = tid & 31;
    int wm = w >> 2, wn = w & 3;   // valid for w < 8

    wmma::fragment<wmma::accumulator,16,16,16,float> acc[2];
    #pragma unroll
    for (int i = 0; i < 2; i++) wmma::fill_fragment(acc[i], 0.f);

    for (int kc = 0; kc < 4; kc++) {
        #pragma unroll
        for (int r = 0; r < 2; r++) {
            int idx = tid + r*512;
            int ar = idx >> 4, ac = (idx & 15) * 4;
            float4 va4 = *(const float4*)(A + (size_t)(row0+ar)*DD + kc*64 + ac);
            __nv_bfloat16 ta[4] = {__float2bfloat16(va4.x), __float2bfloat16(va4.y),
                                   __float2bfloat16(va4.z), __float2bfloat16(va4.w)};
            *(uint2*)(&As[ar][ac]) = *(uint2*)ta;
            float4 vb4 = *(const float4*)(B + (size_t)(kc*64+ar)*DD + col0 + ac);
            __nv_bfloat16 tb[4] = {__float2bfloat16(vb4.x), __float2bfloat16(vb4.y),
                                   __float2bfloat16(vb4.z), __float2bfloat16(vb4.w)};
            *(uint2*)(&Bs[ar][ac]) = *(uint2*)tb;
        }
        __syncthreads();
        if (w < 8) {
            #pragma unroll
            for (int k4 = 0; k4 < 4; k4++) {
                wmma::fragment<wmma::matrix_a,16,16,16,__nv_bfloat16,wmma::row_major> af[2];
                wmma::fragment<wmma::matrix_b,16,16,16,__nv_bfloat16,wmma::row_major> bf;
                #pragma unroll
                for (int i = 0; i < 2; i++)
                    wmma::load_matrix_sync(af[i], &As[wm*32 + i*16][k4*16], 72);
                wmma::load_matrix_sync(bf, &Bs[k4*16][wn*16], 72);
                #pragma unroll
                for (int i = 0; i < 2; i++)
                    wmma::mma_sync(acc[i], af[i], bf, acc[i]);
            }
        }
        __syncthreads();
    }
    if (w < 8) {
        int r = lane >> 1, c8 = (lane & 1) * 8;
        #pragma unroll
        for (int i = 0; i < 2; i++) {
            wmma::store_matrix_sync(&epi[w][0][0], acc[i], 16, wmma::mem_row_major);
            __syncwarp();
            int gr = row0 + wm*32 + i*16 + r;
            int gc = col0 + wn*16 + c8;
            __nv_bfloat16 t8[8];
            #pragma unroll
            for (int e = 0; e < 8; e++)
                t8[e] = __float2bfloat16(epi[w][r][c8+e]);
            *(uint4*)(g_Wffb + (size_t)gr*DD + gc) = *(uint4*)t8;
            __syncwarp();
        }
    }
}

// ================= prep0: conv(x, Wqkv) || agent_proj || Wff ================
__global__ void __launch_bounds__(512) prep0(const float* __restrict__ x,
                                             const float* __restrict__ Wqkv,
                                             const float* __restrict__ Wfc1,
                                             const float* __restrict__ Wfc2,
                                             const float* __restrict__ agent,
                                             const float* __restrict__ Wag,
                                             const float* __restrict__ bag) {
    extern __shared__ __align__(16) char smp[];
    if (blockIdx.x < 1024) {
        int tid = blockIdx.x * 512 + threadIdx.x;
        int stride = 1024 * 512;
        for (int i = tid; i < (MTOK*DD)/4; i += stride) {
            float4 v = *(const float4*)(x + i*4);
            __nv_bfloat16 t[4] = {__float2bfloat16(v.x), __float2bfloat16(v.y),
                                  __float2bfloat16(v.z), __float2bfloat16(v.w)};
            *(uint2*)(g_xb + i*4) = *(uint2*)t;
        }
        for (int i = tid; i < DD*W3; i += stride)
            g_Wqkvb[i] = __float2bfloat16(Wqkv[i]);
    } else if (blockIdx.x < 1088) {
        __shared__ float arow[DD];
        int a = blockIdx.x - 1024;
        for (int i = threadIdx.x; i < DD; i += 512)
            arow[i] = agent[a*DD + i];
        __syncthreads();
        int o = threadIdx.x;  // 0..511
        float s = 0.f;
        #pragma unroll 8
        for (int d = 0; d < DD; d++)
            s += arow[d] * Wag[d*2*DD + o];
        s += bag[o];
        s *= 0.0625f;  // 256^-0.5
        if (o < DD) {
            g_qasb[a*DD + o] = __float2bfloat16(s);
        } else {
            g_kasb[a*DD + (o-DD)] = __float2bfloat16(s);
            g_kaf [a*DD + (o-DD)] = s;
        }
    } else {
        int t = blockIdx.x - 1088;
        dev_wff(smp, t & 3, t >> 2, Wfc1, Wfc2);
    }
}

// ---------------- device: proj_agents tile (256 thr) -------------------------
__device__ void dev_proj_agents(char* sm, int ix, int sel) {
    __nv_bfloat16 (*Aa)[64][40] = (__nv_bfloat16(*)[64][40]) sm;
    __nv_bfloat16 (*Ws)[64][40] = (__nv_bfloat16(*)[64][40])(sm + 10240);
    float (*epi)[16][16]        = (float(*)[16][16])        (sm + 20480);
    uint32_t sA = smem_u32(sm), sW = sA + 10240u;

    int col0 = ix * 64;
    const __nv_bfloat16* A  = sel ? g_kasb : g_qasb;
    const __nv_bfloat16* Bb = g_Wqkvb + (sel ? 0 : DD);
    __nv_bfloat16* C = sel ? g_kat : g_qap;
    int tid = threadIdx.x;
    int w = tid >> 5, lane = tid & 31;
    int wm = w >> 2, wn = w & 3;

    wmma::fragment<wmma::accumulator,16,16,16,float> acc[2];
    #pragma unroll
    for (int i = 0; i < 2; i++) wmma::fill_fragment(acc[i], 0.f);

    #define PA_STAGE(kc, bb) {                                                     \
        {   int ar = tid >> 2, ac = (tid & 3) * 8;                                 \
            CPA16(sA + (uint32_t)(bb)*5120u + (uint32_t)ar*80u + (uint32_t)ac*2u,  \
                  A + (size_t)ar*DD + (kc) + ac); }                                \
        {   int wr = tid >> 2, wc = (tid & 3) * 8;                                 \
            CPA16(sW + (uint32_t)(bb)*5120u + (uint32_t)wr*80u + (uint32_t)wc*2u,  \
                  Bb + (size_t)(col0 + wr)*W3 + (kc) + wc); }                      \
        CPA_COMMIT(); }

    PA_STAGE(0, 0);
    for (int s = 0; s < 8; s++) {
        CPA_WAIT(0);
        __syncthreads();
        if (s < 7) PA_STAGE((s+1)*32, (s+1)&1);
        int bb = s & 1;
        #pragma unroll
        for (int kk = 0; kk < 2; kk++) {
            wmma::fragment<wmma::matrix_a,16,16,16,__nv_bfloat16,wmma::row_major> af[2];
            wmma::fragment<wmma::matrix_b,16,16,16,__nv_bfloat16,wmma::col_major> bf;
            #pragma unroll
            for (int i = 0; i < 2; i++)
                wmma::load_matrix_sync(af[i], &Aa[bb][wm*32 + i*16][kk*16], 40);
            wmma::load_matrix_sync(bf, &Ws[bb][wn*16][kk*16], 40);
            #pragma unroll
            for (int i = 0; i < 2; i++)
                wmma::mma_sync(acc[i], af[i], bf, acc[i]);
        }
    }
    #undef PA_STAGE

    #pragma unroll
    for (int i = 0; i < 2; i++) {
        wmma::store_matrix_sync(&epi[w][0][0], acc[i], 16, wmma::mem_row_major);
        __syncwarp();
        if (lane < 16) {
            int a = wm*32 + i*16 + lane;
            __nv_bfloat16 t8[8];
            #pragma unroll
            for (int g = 0; g < 2; g++) {
                #pragma unroll
                for (int e = 0; e < 8; e++)
                    t8[e] = __float2bfloat16(epi[w][lane][g*8+e]);
                *(uint4*)(C + (size_t)a*DD + col0 + wn*16 + g*8) = *(uint4*)t8;
            }
        }
        __syncwarp();
    }
}

// ---------------- device: Wvf2 tile = Wv @ Wffb (cp.async, bf16 out) ---------
__device__ void dev_wvf2(char* sm, int bx, int by) {
    __nv_bfloat16 (*As)[64][72] = (__nv_bfloat16(*)[64][72]) sm;
    __nv_bfloat16 (*Bs)[64][72] = (__nv_bfloat16(*)[64][72])(sm + 18432);
    float (*epi)[16][16]        = (float(*)[16][16])        (sm + 36864);
    uint32_t sA = smem_u32(sm), sB = sA + 18432u;

    int row0 = by * 64, col0 = bx * 64;
    const __nv_bfloat16* A = g_Wqkvb + 2*DD;   // Wv rows, lda = W3
    const __nv_bfloat16* B = g_Wffb;           // lda = DD
    int tid = threadIdx.x, w = tid >> 5, lane = tid & 31;
    int wm = w >> 2, wn = w & 3;

    wmma::fragment<wmma::accumulator,16,16,16,float> acc[2];
    #pragma unroll
    for (int i = 0; i < 2; i++) wmma::fill_fragment(acc[i], 0.f);

    #define WV_STAGE(kc, bb) {                                                     \
        _Pragma("unroll")                                                          \
        for (int r = 0; r < 2; r++) {                                              \
            int idx = tid + r*256;                                                 \
            int ar = idx >> 3, ac = (idx & 7) * 8;                                 \
            CPA16(sA + (uint32_t)(bb)*9216u + (uint32_t)ar*144u + (uint32_t)ac*2u, \
                  A + (size_t)(row0+ar)*W3 + (kc) + ac);                           \
        }                                                                          \
        _Pragma("unroll")                                                          \
        for (int r = 0; r < 2; r++) {                                              \
            int idx = tid + r*256;                                                 \
            int br = idx >> 3, bc = (idx & 7) * 8;                                 \
            CPA16(sB + (uint32_t)(bb)*9216u + (uint32_t)br*144u + (uint32_t)bc*2u, \
                  B + (size_t)((kc)+br)*DD + col0 + bc);                           \
        }                                                                          \
        CPA_COMMIT(); }

    WV_STAGE(0, 0);
    for (int s = 0; s < 4; s++) {
        CPA_WAIT(0);
        __syncthreads();
        if (s < 3) WV_STAGE((s+1)*64, (s+1)&1);
        int bb = s & 1;
        #pragma unroll
        for (int k4 = 0; k4 < 4; k4++) {
            wmma::fragment<wmma::matrix_a,16,16,16,__nv_bfloat16,wmma::row_major> af[2];
            wmma::fragment<wmma::matrix_b,16,16,16,__nv_bfloat16,wmma::row_major> bf;
            #pragma unroll
            for (int i = 0; i < 2; i++)
                wmma::load_matrix_sync(af[i], &As[bb][wm*32 + i*16][k4*16], 72);
            wmma::load_matrix_sync(bf, &Bs[bb][k4*16][wn*16], 72);
            #pragma unroll
            for (int i = 0; i < 2; i++)
                wmma::mma_sync(acc[i], af[i], bf, acc[i]);
        }
    }
    #undef WV_STAGE
    __syncthreads();

    int r = lane >> 1, c8 = (lane & 1) * 8;
    #pragma unroll
    for (int i = 0; i < 2; i++) {
        wmma::store_matrix_sync(&epi[w][0][0], acc[i], 16, wmma::mem_row_major);
        __syncwarp();
        int gr = row0 + wm*32 + i*16 + r;
        int gc = col0 + wn*16 + c8;
        __nv_bfloat16 t8[8];
        #pragma unroll
        for (int e = 0; e < 8; e++)
            t8[e] = __float2bfloat16(epi[w][r][c8+e]);
        *(uint4*)(g_Wvf2b + (size_t)gr*DD + gc) = *(uint4*)t8;
        __syncwarp();
    }
}

// ===== prep1: proj_agents || Wvf2 || dbias || bvf2 (grid 89, 256 thr) ========
__global__ void __launch_bounds__(256) prep1(const float* __restrict__ bqkv,
                                             const float* __restrict__ Wfc1,
                                             const float* __restrict__ bfc1,
                                             const float* __restrict__ Wfc2) {
    extern __shared__ __align__(16) char sm[];
    int bid = blockIdx.x;
    if (bid < 8) {
        dev_proj_agents(sm, bid & 3, bid >> 2);
    } else if (bid < 24) {
        int t = bid - 8;
        dev_wvf2(sm, t & 3, t >> 2);
    } else if (bid < 88) {
        float* red = (float*)sm;
        int a = bid - 24, i = threadIdx.x;
        red[i] = bqkv[i] * g_kaf[a*DD + i];
        __syncthreads();
        for (int st = 128; st > 0; st >>= 1) {
            if (i < st) red[i] += red[i + st];
            __syncthreads();
        }
        if (i == 0) g_dbias[a] = red[0];
    } else {
        // bvf2 = (bv@Wfc1 + bfc1) @ Wfc2, two chained GEMVs
        float* bvf = (float*)sm;
        int j = threadIdx.x;
        float t = bfc1[j];
        #pragma unroll 8
        for (int o = 0; o < DD; o++)
            t += bqkv[2*DD + o] * Wfc1[o*DD + j];
        bvf[j] = t;
        __syncthreads();
        float t2 = 0.f;
        #pragma unroll 8
        for (int o = 0; o < DD; o++)
            t2 += bvf[o] * Wfc2[o*DD + j];
        g_bvf2[j] = t2;
    }
}

// ======== fused stage-1 (SPL=32, X-resident): logits -> softmax -> u =========
// smem: X[128][264]@0 (67584) | Qa 2x[64][40]@67584 (10240) | L[64][136]@77824 (17408)
//       epi[8][16][16]@95232 (8192). total 103424
__global__ void __launch_bounds__(256, 2) s1fused() {
    extern __shared__ __align__(16) char smf[];
    __nv_bfloat16 (*X)[264]     = ( __nv_bfloat16(*)[264]) smf;
    __nv_bfloat16 (*Qa)[64][40] = ( __nv_bfloat16(*)[64][40]) (smf + 67584);
    __nv_bfloat16 (*L)[136]     = ( __nv_bfloat16(*)[136])    (smf + 77824);
    float (*epi)[16][16]        = ( float(*)[16][16])         (smf + 95232);
    uint32_t sX = smem_u32(smf);
    uint32_t sQ = sX + 67584u;

    int split = blockIdx.x, b = blockIdx.y;
    int tok0 = split * TSPL;
    int tid = threadIdx.x;
    int w = tid >> 5, lane = tid & 31;
    int wm = w >> 2, wn = w & 3;

    // ---- pass 1: logits[64,128], staging X chunks (distinct col ranges) ----
    #define F1_STAGE(kc, bb) {                                                     \
        {   int ar = tid >> 2, ac = (tid & 3) * 8;                                 \
            CPA16(sQ + (uint32_t)(bb)*5120u + (uint32_t)ar*80u + (uint32_t)ac*2u,  \
                  g_qap + (size_t)ar*DD + (kc) + ac); }                            \
        _Pragma("unroll")                                                          \
        for (int r = 0; r < 2; r++) {                                              \
            int idx = tid + r*256;                                                 \
            int xr = idx >> 2, xc = (idx & 3) * 8;                                 \
            CPA16(sX + (uint32_t)xr*528u + (uint32_t)((kc) + xc)*2u,               \
                  g_xb + (size_t)(b*NT + tok0 + xr)*DD + (kc) + xc);               \
        }                                                                          \
        CPA_COMMIT(); }

    {
        wmma::fragment<wmma::accumulator,16,16,16,float> acc[2][2];
        #pragma unroll
        for (int i = 0; i < 2; i++)
            #pragma unroll
            for (int j = 0; j < 2; j++) wmma::fill_fragment(acc[i][j], 0.f);

        F1_STAGE(0, 0);
        for (int s = 0; s < 8; s++) {
            CPA_WAIT(0);
            __syncthreads();
            if (s < 7) F1_STAGE((s+1)*32, (s+1)&1);
            int bb = s & 1;
            #pragma unroll
            for (int kk = 0; kk < 2; kk++) {
                wmma::fragment<wmma::matrix_a,16,16,16,__nv_bfloat16,wmma::row_major> af[2];
                wmma::fragment<wmma::matrix_b,16,16,16,__nv_bfloat16,wmma::col_major> bf[2];
                #pragma unroll
                for (int i = 0; i < 2; i++)
                    wmma::load_matrix_sync(af[i], &Qa[bb][wm*32 + i*16][kk*16], 40);
                #pragma unroll
                for (int j = 0; j < 2; j++)
                    wmma::load_matrix_sync(bf[j], &X[wn*32 + j*16][s*32 + kk*16], 264);
                #pragma unroll
                for (int i = 0; i < 2; i++)
                    #pragma unroll
                    for (int j = 0; j < 2; j++)
                        wmma::mma_sync(acc[i][j], af[i], bf[j], acc[i][j]);
            }
        }
        __syncthreads();
        #pragma unroll
        for (int i = 0; i < 2; i++)
            #pragma unroll
            for (int j = 0; j < 2; j++) {
                wmma::store_matrix_sync(&epi[w][0][0], acc[i][j], 16, wmma::mem_row_major);
                __syncwarp();
                if (lane < 16) {
                    int ga = wm*32 + i*16 + lane;
                    int gc = wn*32 + j*16;
                    __nv_bfloat16 t8[8];
                    #pragma unroll
                    for (int g = 0; g < 2; g++) {
                        #pragma unroll
                        for (int e = 0; e < 8; e++)
                            t8[e] = __float2bfloat16(epi[w][lane][g*8+e]);
                        *(uint4*)(&L[ga][gc + g*8]) = *(uint4*)t8;
                    }
                }
                __syncwarp();
            }
        __syncthreads();
    }
    #undef F1_STAGE

    // ---- split softmax over 128 cols: row = tid>>2, 4 threads/row ----
    {
        int row = tid >> 2, q = tid & 3;
        float m = -1e30f;
        #pragma unroll 8
        for (int c = 0; c < 32; c++)
            m = fmaxf(m, __bfloat162float(L[row][q*32 + c]));
        m = fmaxf(m, __shfl_xor_sync(0xffffffffu, m, 1));
        m = fmaxf(m, __shfl_xor_sync(0xffffffffu, m, 2));
        float sum = 0.f;
        #pragma unroll 8
        for (int c = 0; c < 32; c++) {
            float p = __expf(__bfloat162float(L[row][q*32 + c]) - m);
            sum += p;
            L[row][q*32 + c] = __float2bfloat16(p);
        }
        sum += __shfl_xor_sync(0xffffffffu, sum, 1);
        sum += __shfl_xor_sync(0xffffffffu, sum, 2);
        if (q == 0)
            g_stats[(b*SPL + split)*NA + row] = make_float2(m, sum);
    }
    __syncthreads();

    // ---- pass 2: u_split[64,256] = P[64,128] @ X[128,256]; no staging ----
    {
        wmma::fragment<wmma::accumulator,16,16,16,float> acc[2][4];
        #pragma unroll
        for (int i = 0; i < 2; i++)
            #pragma unroll
            for (int j = 0; j < 4; j++) wmma::fill_fragment(acc[i][j], 0.f);

        #pragma unroll
        for (int kk = 0; kk < 8; kk++) {
            wmma::fragment<wmma::matrix_a,16,16,16,__nv_bfloat16,wmma::row_major> af[2];
            wmma::fragment<wmma::matrix_b,16,16,16,__nv_bfloat16,wmma::row_major> bf[4];
            #pragma unroll
            for (int i = 0; i < 2; i++)
                wmma::load_matrix_sync(af[i], &L[wm*32 + i*16][kk*16], 136);
            #pragma unroll
            for (int j = 0; j < 4; j++)
                wmma::load_matrix_sync(bf[j], &X[kk*16][wn*64 + j*16], 264);
            #pragma unroll
            for (int i = 0; i < 2; i++)
                #pragma unroll
                for (int j = 0; j < 4; j++)
                    wmma::mma_sync(acc[i][j], af[i], bf[j], acc[i][j]);
        }
        __syncthreads();

        __nv_bfloat16* outb = g_vapb + (size_t)(b*SPL + split)*NA*DD;
        #pragma unroll
        for (int i = 0; i < 2; i++)
            #pragma unroll
            for (int j = 0; j < 4; j++) {
                wmma::store_matrix_sync(&epi[w][0][0], acc[i][j], 16, wmma::mem_row_major);
                __syncwarp();
                #pragma unroll
                for (int e = 0; e < 2; e++) {
                    int idx2 = lane + e*32;
                    int r = idx2 >> 2, c4 = (idx2 & 3) * 4;
                    int ga = wm*32 + i*16 + r;
                    int gd = wn*64 + j*16 + c4;
                    __nv_bfloat16 t4[4];
                    #pragma unroll
                    for (int e2 = 0; e2 < 4; e2++)
                        t4[e2] = __float2bfloat16(epi[w][r][c4+e2]);
                    *(uint2*)(outb + (size_t)ga*DD + gd) = *(uint2*)t4;
                }
                __syncwarp();
            }
    }
}

// ---------------- combine (vectorized): log-sum-exp merge -> u bf16 ---------
// grid 128, block 256: 4 rows/block, 64 thr/row, 4 elems/thread (uint2)
__global__ void __launch_bounds__(256) combine_k() {
    __shared__ float ms[4][SPL], ss[4][SPL];
    int r0 = blockIdx.x * 4;
    int tid = threadIdx.x;
    int lrow = tid >> 6;             // 0..3
    int q = tid & 63;                // elem group (4 elems)
    int row = r0 + lrow;
    int b = row >> 6, a = row & 63;

    if (tid < 128) {
        int rr = tid >> 5, s = tid & 31;
        int rg = r0 + rr;
        float2 st = g_stats[((rg >> 6)*SPL + s)*NA + (rg & 63)];
        ms[rr][s] = st.x; ss[rr][s] = st.y;
    }
    __syncthreads();

    float m = -1e30f;
    #pragma unroll
    for (int s = 0; s < SPL; s++) m = fmaxf(m, ms[lrow][s]);
    float S = 0.f;
    float wsc[SPL];
    #pragma unroll
    for (int s = 0; s < SPL; s++) {
        wsc[s] = __expf(ms[lrow][s] - m);
        S += wsc[s] * ss[lrow][s];
    }
    float invS = 1.f / S;

    float acc[4] = {0.f, 0.f, 0.f, 0.f};
    const __nv_bfloat16* base = g_vapb + (size_t)b*SPL*NA*DD + (size_t)a*DD + q*4;
    #pragma unroll
    for (int s = 0; s < SPL; s++) {
        __nv_bfloat16 t4[4];
        *(uint2*)t4 = *(const uint2*)(base + (size_t)s*NA*DD);
        #pragma unroll
        for (int e = 0; e < 4; e++)
            acc[e] += wsc[s] * __bfloat162float(t4[e]);
    }
    __nv_bfloat16 o4[4];
    #pragma unroll
    for (int e = 0; e < 4; e++)
        o4[e] = __float2bfloat16(acc[e] * invS);
    *(uint2*)(g_ub + (size_t)row*DD + q*4) = *(uint2*)o4;
}

// ---------------- fc2v: va2[512,256] = u @ Wvf2b + bvf2 (WMMA) ---------------
__global__ void __launch_bounds__(256) fc2v() {
    __shared__ __nv_bfloat16 As[2][64][72];
    __shared__ __nv_bfloat16 Bs[2][64][72];
    __shared__ float epi[8][16][16];
    uint32_t sA = smem_u32(&As[0][0][0]), sB = smem_u32(&Bs[0][0][0]);

    int row0 = blockIdx.y * 64, col0 = blockIdx.x * 64;
    int tid = threadIdx.x, w = tid >> 5, lane = tid & 31;
    int wm = w >> 2, wn = w & 3;

    wmma::fragment<wmma::accumulator,16,16,16,float> acc[2];
    #pragma unroll
    for (int i = 0; i < 2; i++) wmma::fill_fragment(acc[i], 0.f);

    #define FV_STAGE(kc, bb) {                                                     \
        _Pragma("unroll")                                                          \
        for (int r = 0; r < 2; r++) {                                              \
            int idx = tid + r*256;                                                 \
            int ar = idx >> 3, ac = (idx & 7) * 8;                                 \
            CPA16(sA + (uint32_t)(bb)*9216u + (uint32_t)ar*144u + (uint32_t)ac*2u, \
                  g_ub + (size_t)(row0+ar)*DD + (kc) + ac);                        \
        }                                                                          \
        _Pragma("unroll")                                                          \
        for (int r = 0; r < 2; r++) {                                              \
            int idx = tid + r*256;                                                 \
            int br = idx >> 3, bc = (idx & 7) * 8;                                 \
            CPA16(sB + (uint32_t)(bb)*9216u + (uint32_t)br*144u + (uint32_t)bc*2u, \
                  g_Wvf2b + (size_t)((kc)+br)*DD + col0 + bc);                     \
        }                                                                          \
        CPA_COMMIT(); }

    FV_STAGE(0, 0);
    for (int s = 0; s < 4; s++) {
        CPA_WAIT(0);
        __syncthreads();
        if (s < 3) FV_STAGE((s+1)*64, (s+1)&1);
        int bb = s & 1;
        #pragma unroll
        for (int k4 = 0; k4 < 4; k4++) {
            wmma::fragment<wmma::matrix_a,16,16,16,__nv_bfloat16,wmma::row_major> af[2];
            wmma::fragment<wmma::matrix_b,16,16,16,__nv_bfloat16,wmma::row_major> bf;
            #pragma unroll
            for (int i = 0; i < 2; i++)
                wmma::load_matrix_sync(af[i], &As[bb][wm*32 + i*16][k4*16], 72);
            wmma::load_matrix_sync(bf, &Bs[bb][k4*16][wn*16], 72);
            #pragma unroll
            for (int i = 0; i < 2; i++)
                wmma::mma_sync(acc[i], af[i], bf, acc[i]);
        }
    }
    #undef FV_STAGE
    __syncthreads();

    int r = lane >> 1, c8 = (lane & 1) * 8;
    #pragma unroll
    for (int i = 0; i < 2; i++) {
        wmma::store_matrix_sync(&epi[w][0][0], acc[i], 16, wmma::mem_row_major);
        __syncwarp();
        int gr = row0 + wm*32 + i*16 + r;
        int gc = col0 + wn*16 + c8;
        __nv_bfloat16 t8[8];
        #pragma unroll
        for (int e = 0; e < 8; e++)
            t8[e] = __float2bfloat16(epi[w][r][c8+e] + g_bvf2[gc+e]);
        *(uint4*)(g_va + (size_t)gr*DD + gc) = *(uint4*)t8;
        __syncwarp();
    }
}

// ======== stage 2 (64-token tiles): logits -> softmax -> P@va2 + bfc2 + x ====
__global__ void __launch_bounds__(256) stage2(const float* __restrict__ bfc2,
                                              const float* __restrict__ x,
                                              float* __restrict__ out) {
    extern __shared__ __align__(16) char sm2[];
    __nv_bfloat16 (*Qs)[64][40] = ( __nv_bfloat16(*)[64][40]) sm2;
    __nv_bfloat16 (*Ka)[64][40] = ( __nv_bfloat16(*)[64][40]) (sm2 + 10240);
    float* logits               = ( float*)                   (sm2 + 20480);
    __nv_bfloat16 (*Vs)[264]    = ( __nv_bfloat16(*)[264])    (sm2 + 37888);
    __nv_bfloat16 (*Pm)[72]     = ( __nv_bfloat16(*)[72])     sm2;
    float (*epi)[16][16]        = ( float(*)[16][16])         (sm2 + 10240);
    __shared__ float dbs[NA];
    uint32_t sQ = smem_u32(sm2), sKa = sQ + 10240u, sV = sQ + 37888u;

    int b = blockIdx.y, t0 = blockIdx.x * 64;
    int tid = threadIdx.x;
    int w = tid >> 5, lane = tid & 31;
    int wm = w >> 2, wn = w & 3;

    if (tid < NA) dbs[tid] = g_dbias[tid];

    #pragma unroll
    for (int r = 0; r < 8; r++) {
        int idx = tid + r*256;
        int vr = idx >> 5, vc = (idx & 31) * 8;
        CPA16(sV + (uint32_t)vr*528u + (uint32_t)vc*2u,
              g_va + (size_t)(b*NA + vr)*DD + vc);
    }
    CPA_COMMIT();

    // --- phase A: logits[64,64] = x_tile[64,256] @ Ka'[64,256]^T ---
    {
        wmma::fragment<wmma::accumulator,16,16,16,float> acc[2];
        #pragma unroll
        for (int i = 0; i < 2; i++) wmma::fill_fragment(acc[i], 0.f);

        #define S2_STAGE(kc, bb) {                                                 \
            {   int qr = tid >> 2, qc = (tid & 3) * 8;                             \
                CPA16(sQ + (uint32_t)(bb)*5120u + (uint32_t)qr*80u + (uint32_t)qc*2u, \
                      g_xb + (size_t)(b*NT + t0 + qr)*DD + (kc) + qc); }           \
            {   int ar = tid >> 2, ac = (tid & 3) * 8;                             \
                CPA16(sKa + (uint32_t)(bb)*5120u + (uint32_t)ar*80u + (uint32_t)ac*2u, \
                      g_kat + (size_t)ar*DD + (kc) + ac); }                        \
            CPA_COMMIT(); }

        S2_STAGE(0, 0);
        for (int s = 0; s < 8; s++) {
            CPA_WAIT(0);
            __syncthreads();
            if (s < 7) S2_STAGE((s+1)*32, (s+1)&1);
            int bb = s & 1;
            #pragma unroll
            for (int kk = 0; kk < 2; kk++) {
                wmma::fragment<wmma::matrix_a,16,16,16,__nv_bfloat16,wmma::row_major> af[2];
                wmma::fragment<wmma::matrix_b,16,16,16,__nv_bfloat16,wmma::col_major> bf;
                #pragma unroll
                for (int i = 0; i < 2; i++)
                    wmma::load_matrix_sync(af[i], &Qs[bb][wm*32 + i*16][kk*16], 40);
                wmma::load_matrix_sync(bf, &Ka[bb][wn*16][kk*16], 40);
                #pragma unroll
                for (int i = 0; i < 2; i++)
                    wmma::mma_sync(acc[i], af[i], bf, acc[i]);
            }
        }
        #undef S2_STAGE
        __syncthreads();
        #pragma unroll
        for (int i = 0; i < 2; i++)
            wmma::store_matrix_sync(logits + (wm*32 + i*16)*68 + wn*16,
                                    acc[i], 68, wmma::mem_row_major);
    }
    __syncthreads();

    // --- phase B: per-row softmax over 64 agents (+dbias); 4 threads/row ---
    {
        int row = tid >> 2, q = tid & 3;
        const float* lr = logits + row*68 + q*16;
        float lv[16];
        #pragma unroll
        for (int c = 0; c < 16; c++) lv[c] = lr[c] + dbs[q*16 + c];
        float m = -1e30f;
        #pragma unroll
        for (int c = 0; c < 16; c++) m = fmaxf(m, lv[c]);
        m = fmaxf(m, __shfl_xor_sync(0xffffffffu, m, 1));
        m = fmaxf(m, __shfl_xor_sync(0xffffffffu, m, 2));
        float sum = 0.f;
        float pv[16];
        #pragma unroll
        for (int c = 0; c < 16; c++) { pv[c] = __expf(lv[c] - m); sum += pv[c]; }
        sum += __shfl_xor_sync(0xffffffffu, sum, 1);
        sum += __shfl_xor_sync(0xffffffffu, sum, 2);
        float inv = 1.f / sum;
        __syncthreads();
        #pragma unroll
        for (int c = 0; c < 16; c++)
            Pm[row][q*16 + c] = __float2bfloat16(pv[c] * inv);
    }
    __syncthreads();

    // --- phase C: out[64,256] = Pm[64,64] @ Vs[64,256] + bfc2 + x ---
    {
        wmma::fragment<wmma::accumulator,16,16,16,float> acc[2][4];
        #pragma unroll
        for (int i = 0; i < 2; i++)
            #pragma unroll
            for (int j = 0; j < 4; j++) wmma::fill_fragment(acc[i][j], 0.f);
        #pragma unroll
        for (int kk = 0; kk < 4; kk++) {
            wmma::fragment<wmma::matrix_a,16,16,16,__nv_bfloat16,wmma::row_major> af[2];
            wmma::fragment<wmma::matrix_b,16,16,16,__nv_bfloat16,wmma::row_major> bf[4];
            #pragma unroll
            for (int i = 0; i < 2; i++)
                wmma::load_matrix_sync(af[i], &Pm[wm*32 + i*16][kk*16], 72);
            #pragma unroll
            for (int j = 0; j < 4; j++)
                wmma::load_matrix_sync(bf[j], &Vs[kk*16][wn*64 + j*16], 264);
            #pragma unroll
            for (int i = 0; i < 2; i++)
                #pragma unroll
                for (int j = 0; j < 4; j++)
                    wmma::mma_sync(acc[i][j], af[i], bf[j], acc[i][j]);
        }
        __syncthreads();
        int r = lane >> 1, c8 = (lane & 1) * 8;
        #pragma unroll
        for (int i = 0; i < 2; i++)
            #pragma unroll
            for (int j = 0; j < 4; j++) {
                wmma::store_matrix_sync(&epi[w][0][0], acc[i][j], 16, wmma::mem_row_major);
                __syncwarp();
                int grow = t0 + wm*32 + i*16 + r;
                int gcol = wn*64 + j*16 + c8;
                size_t gi = (size_t)(b*NT + grow)*DD + gcol;
                float o0[4], o1[4];
                #pragma unroll
                for (int e = 0; e < 4; e++)
                    o0[e] = epi[w][r][c8+e]   + bfc2[gcol+e]   + x[gi+e];
                #pragma unroll
                for (int e = 0; e < 4; e++)
                    o1[e] = epi[w][r][c8+4+e] + bfc2[gcol+4+e] + x[gi+4+e];
                *(float4*)(out + gi)     = *(float4*)o0;
                *(float4*)(out + gi + 4) = *(float4*)o1;
                __syncwarp();
            }
    }
}

// ---------------- launcher ---------------------------------------------------
#define S1F_SMEM 103424
#define S2_SMEM  71680
#define PREP_SMEM 45056

extern "C" void kernel_launch(void* const* d_in, const int* in_sizes, int n_in,
                              void* d_out, int out_size) {
    const float* agent = (const float*)d_in[0];
    const float* x     = (const float*)d_in[1];
    const float* Wqkv  = (const float*)d_in[2];
    const float* bqkv  = (const float*)d_in[3];
    const float* Wag   = (const float*)d_in[4];
    const float* bag   = (const float*)d_in[5];
    const float* Wfc1  = (const float*)d_in[6];
    const float* bfc1  = (const float*)d_in[7];
    const float* Wfc2  = (const float*)d_in[8];
    const float* bfc2  = (const float*)d_in[9];
    float* out = (float*)d_out;

    cudaFuncSetAttribute(s1fused, cudaFuncAttributeMaxDynamicSharedMemorySize, S1F_SMEM);
    cudaFuncSetAttribute(stage2,  cudaFuncAttributeMaxDynamicSharedMemorySize, S2_SMEM);
    cudaFuncSetAttribute(prep0,   cudaFuncAttributeMaxDynamicSharedMemorySize, PREP_SMEM);

    prep0<<<1104, 512, PREP_SMEM>>>(x, Wqkv, Wfc1, Wfc2, agent, Wag, bag);
    prep1<<<89, 256, PREP_SMEM>>>(bqkv, Wfc1, bfc1, Wfc2);
    s1fused<<<dim3(SPL, NB), 256, S1F_SMEM>>>();
    combine_k<<<128, 256>>>();
    fc2v<<<dim3(4, 8), 256>>>();
    stage2<<<dim3(64, 8), 256, S2_SMEM>>>(bfc2, x, out);
}

// round 16
// speedup vs baseline: 1.2644x; 1.1384x over previous
#include <cuda_runtime.h>
#include <cuda_bf16.h>
#include <mma.h>
#include <cstdint>

using namespace nvcuda;

#define NB 8
#define NT 4096
#define NA 64
#define DD 256
#define MTOK (NB*NT)
#define W3 (3*DD)
#define SPL 32
#define TSPL 128   // tokens per split

// ---------------- scratch (device globals; no allocations allowed) ----------
__device__ __nv_bfloat16 g_Wqkvb[DD*W3];             // W_qkv bf16 [K, 3N]
__device__ __nv_bfloat16 g_Wffb[DD*DD];              // Wfc1@Wfc2 bf16
__device__ __nv_bfloat16 g_qasb[NA*DD];              // qa_s bf16 (scale folded)
__device__ __nv_bfloat16 g_kasb[NA*DD];              // ka_s bf16 (scale folded)
__device__ float        g_kaf[NA*DD];                // ka_s fp32 (for dbias)
__device__ __nv_bfloat16 g_qap[NA*DD];               // qa' = qa_s @ Wk^T, bf16
__device__ __nv_bfloat16 g_kat[NA*DD];               // Ka' [a,i] bf16
__device__ float        g_dbias[NA];                 // bq . ka_s
__device__ __nv_bfloat16 g_Wvf2b[DD*DD];             // Wv@(Wfc1@Wfc2), bf16
__device__ float        g_bvf2[DD];                  // (bv@Wfc1+bfc1)@Wfc2
__device__ __nv_bfloat16 g_vapb[NB*SPL*NA*DD];       // unnormalized split partials (bf16)
__device__ float2       g_stats[NB*SPL*NA];          // (m_s, s_s) per split-row
__device__ __nv_bfloat16 g_ub[NB*NA*DD];             // combined u, bf16
__device__ __nv_bfloat16 g_va[NB*NA*DD];             // va2 bf16

// ---------------- cp.async helpers ------------------------------------------
__device__ __forceinline__ uint32_t smem_u32(const void* p) {
    uint32_t a;
    asm("{ .reg .u64 t; cvta.to.shared.u64 t, %1; cvt.u32.u64 %0, t; }" : "=r"(a) : "l"(p));
    return a;
}
#define CPA16(s, g)  asm volatile("cp.async.cg.shared.global [%0], [%1], 16;" :: "r"(s), "l"(g))
#define CPA_COMMIT() asm volatile("cp.async.commit_group;" ::: "memory")
#define CPA_WAIT(n)  asm volatile("cp.async.wait_group %0;" :: "n"(n) : "memory")

__device__ __forceinline__ void cvt8(__nv_bfloat16* t8, float4 v0, float4 v1) {
    t8[0] = __float2bfloat16(v0.x); t8[1] = __float2bfloat16(v0.y);
    t8[2] = __float2bfloat16(v0.z); t8[3] = __float2bfloat16(v0.w);
    t8[4] = __float2bfloat16(v1.x); t8[5] = __float2bfloat16(v1.y);
    t8[6] = __float2bfloat16(v1.z); t8[7] = __float2bfloat16(v1.w);
}

// ---------------- device: Wff tile = Wfc1@Wfc2 (fp32 src, 512 threads) -------
__device__ void dev_wff(char* sm, int bx, int by,
                        const float* __restrict__ A, const float* __restrict__ B) {
    __nv_bfloat16 (*As)[72] = (__nv_bfloat16(*)[72]) sm;
    __nv_bfloat16 (*Bs)[72] = (__nv_bfloat16(*)[72])(sm + 9216);
    float (*epi)[16][16]    = (float(*)[16][16])    (sm + 18432);
    int row0 = by*64, col0 = bx*64;
    int tid = threadIdx.x, w = tid >> 5, lane = tid & 31;
    int wm = w >> 2, wn = w & 3;   // valid for w < 8

    wmma::fragment<wmma::accumulator,16,16,16,float> acc[2];
    #pragma unroll
    for (int i = 0; i < 2; i++) wmma::fill_fragment(acc[i], 0.f);

    for (int kc = 0; kc < 4; kc++) {
        #pragma unroll
        for (int r = 0; r < 2; r++) {
            int idx = tid + r*512;
            int ar = idx >> 4, ac = (idx & 15) * 4;
            float4 va4 = *(const float4*)(A + (size_t)(row0+ar)*DD + kc*64 + ac);
            __nv_bfloat16 ta[4] = {__float2bfloat16(va4.x), __float2bfloat16(va4.y),
                                   __float2bfloat16(va4.z), __float2bfloat16(va4.w)};
            *(uint2*)(&As[ar][ac]) = *(uint2*)ta;
            float4 vb4 = *(const float4*)(B + (size_t)(kc*64+ar)*DD + col0 + ac);
            __nv_bfloat16 tb[4] = {__float2bfloat16(vb4.x), __float2bfloat16(vb4.y),
                                   __float2bfloat16(vb4.z), __float2bfloat16(vb4.w)};
            *(uint2*)(&Bs[ar][ac]) = *(uint2*)tb;
        }
        __syncthreads();
        if (w < 8) {
            #pragma unroll
            for (int k4 = 0; k4 < 4; k4++) {
                wmma::fragment<wmma::matrix_a,16,16,16,__nv_bfloat16,wmma::row_major> af[2];
                wmma::fragment<wmma::matrix_b,16,16,16,__nv_bfloat16,wmma::row_major> bf;
                #pragma unroll
                for (int i = 0; i < 2; i++)
                    wmma::load_matrix_sync(af[i], &As[wm*32 + i*16][k4*16], 72);
                wmma::load_matrix_sync(bf, &Bs[k4*16][wn*16], 72);
                #pragma unroll
                for (int i = 0; i < 2; i++)
                    wmma::mma_sync(acc[i], af[i], bf, acc[i]);
            }
        }
        __syncthreads();
    }
    if (w < 8) {
        int r = lane >> 1, c8 = (lane & 1) * 8;
        #pragma unroll
        for (int i = 0; i < 2; i++) {
            wmma::store_matrix_sync(&epi[w][0][0], acc[i], 16, wmma::mem_row_major);
            __syncwarp();
            int gr = row0 + wm*32 + i*16 + r;
            int gc = col0 + wn*16 + c8;
            __nv_bfloat16 t8[8];
            #pragma unroll
            for (int e = 0; e < 8; e++)
                t8[e] = __float2bfloat16(epi[w][r][c8+e]);
            *(uint4*)(g_Wffb + (size_t)gr*DD + gc) = *(uint4*)t8;
            __syncwarp();
        }
    }
}

// ================= prep0: conv(Wqkv) || agent_proj || Wff (grid 112) ========
__global__ void __launch_bounds__(512) prep0(const float* __restrict__ Wqkv,
                                             const float* __restrict__ Wfc1,
                                             const float* __restrict__ Wfc2,
                                             const float* __restrict__ agent,
                                             const float* __restrict__ Wag,
                                             const float* __restrict__ bag) {
    extern __shared__ __align__(16) char smp[];
    if (blockIdx.x < 32) {
        int tid = blockIdx.x * 512 + threadIdx.x;
        int stride = 32 * 512;
        for (int i = tid; i < DD*W3; i += stride)
            g_Wqkvb[i] = __float2bfloat16(Wqkv[i]);
    } else if (blockIdx.x < 96) {
        __shared__ float arow[DD];
        int a = blockIdx.x - 32;
        for (int i = threadIdx.x; i < DD; i += 512)
            arow[i] = agent[a*DD + i];
        __syncthreads();
        int o = threadIdx.x;  // 0..511
        float s = 0.f;
        #pragma unroll 8
        for (int d = 0; d < DD; d++)
            s += arow[d] * Wag[d*2*DD + o];
        s += bag[o];
        s *= 0.0625f;  // 256^-0.5
        if (o < DD) {
            g_qasb[a*DD + o] = __float2bfloat16(s);
        } else {
            g_kasb[a*DD + (o-DD)] = __float2bfloat16(s);
            g_kaf [a*DD + (o-DD)] = s;
        }
    } else {
        int t = blockIdx.x - 96;
        dev_wff(smp, t & 3, t >> 2, Wfc1, Wfc2);
    }
}

// ---------------- device: proj_agents tile (256 thr) -------------------------
__device__ void dev_proj_agents(char* sm, int ix, int sel) {
    __nv_bfloat16 (*Aa)[64][40] = (__nv_bfloat16(*)[64][40]) sm;
    __nv_bfloat16 (*Ws)[64][40] = (__nv_bfloat16(*)[64][40])(sm + 10240);
    float (*epi)[16][16]        = (float(*)[16][16])        (sm + 20480);
    uint32_t sA = smem_u32(sm), sW = sA + 10240u;

    int col0 = ix * 64;
    const __nv_bfloat16* A  = sel ? g_kasb : g_qasb;
    const __nv_bfloat16* Bb = g_Wqkvb + (sel ? 0 : DD);
    __nv_bfloat16* C = sel ? g_kat : g_qap;
    int tid = threadIdx.x;
    int w = tid >> 5, lane = tid & 31;
    int wm = w >> 2, wn = w & 3;

    wmma::fragment<wmma::accumulator,16,16,16,float> acc[2];
    #pragma unroll
    for (int i = 0; i < 2; i++) wmma::fill_fragment(acc[i], 0.f);

    #define PA_STAGE(kc, bb) {                                                     \
        {   int ar = tid >> 2, ac = (tid & 3) * 8;                                 \
            CPA16(sA + (uint32_t)(bb)*5120u + (uint32_t)ar*80u + (uint32_t)ac*2u,  \
                  A + (size_t)ar*DD + (kc) + ac); }                                \
        {   int wr = tid >> 2, wc = (tid & 3) * 8;                                 \
            CPA16(sW + (uint32_t)(bb)*5120u + (uint32_t)wr*80u + (uint32_t)wc*2u,  \
                  Bb + (size_t)(col0 + wr)*W3 + (kc) + wc); }                      \
        CPA_COMMIT(); }

    PA_STAGE(0, 0);
    for (int s = 0; s < 8; s++) {
        CPA_WAIT(0);
        __syncthreads();
        if (s < 7) PA_STAGE((s+1)*32, (s+1)&1);
        int bb = s & 1;
        #pragma unroll
        for (int kk = 0; kk < 2; kk++) {
            wmma::fragment<wmma::matrix_a,16,16,16,__nv_bfloat16,wmma::row_major> af[2];
            wmma::fragment<wmma::matrix_b,16,16,16,__nv_bfloat16,wmma::col_major> bf;
            #pragma unroll
            for (int i = 0; i < 2; i++)
                wmma::load_matrix_sync(af[i], &Aa[bb][wm*32 + i*16][kk*16], 40);
            wmma::load_matrix_sync(bf, &Ws[bb][wn*16][kk*16], 40);
            #pragma unroll
            for (int i = 0; i < 2; i++)
                wmma::mma_sync(acc[i], af[i], bf, acc[i]);
        }
    }
    #undef PA_STAGE

    #pragma unroll
    for (int i = 0; i < 2; i++) {
        wmma::store_matrix_sync(&epi[w][0][0], acc[i], 16, wmma::mem_row_major);
        __syncwarp();
        if (lane < 16) {
            int a = wm*32 + i*16 + lane;
            __nv_bfloat16 t8[8];
            #pragma unroll
            for (int g = 0; g < 2; g++) {
                #pragma unroll
                for (int e = 0; e < 8; e++)
                    t8[e] = __float2bfloat16(epi[w][lane][g*8+e]);
                *(uint4*)(C + (size_t)a*DD + col0 + wn*16 + g*8) = *(uint4*)t8;
            }
        }
        __syncwarp();
    }
}

// ---------------- device: Wvf2 tile = Wv @ Wffb (cp.async, bf16 out) ---------
__device__ void dev_wvf2(char* sm, int bx, int by) {
    __nv_bfloat16 (*As)[64][72] = (__nv_bfloat16(*)[64][72]) sm;
    __nv_bfloat16 (*Bs)[64][72] = (__nv_bfloat16(*)[64][72])(sm + 18432);
    float (*epi)[16][16]        = (float(*)[16][16])        (sm + 36864);
    uint32_t sA = smem_u32(sm), sB = sA + 18432u;

    int row0 = by * 64, col0 = bx * 64;
    const __nv_bfloat16* A = g_Wqkvb + 2*DD;   // Wv rows, lda = W3
    const __nv_bfloat16* B = g_Wffb;           // lda = DD
    int tid = threadIdx.x, w = tid >> 5, lane = tid & 31;
    int wm = w >> 2, wn = w & 3;

    wmma::fragment<wmma::accumulator,16,16,16,float> acc[2];
    #pragma unroll
    for (int i = 0; i < 2; i++) wmma::fill_fragment(acc[i], 0.f);

    #define WV_STAGE(kc, bb) {                                                     \
        _Pragma("unroll")                                                          \
        for (int r = 0; r < 2; r++) {                                              \
            int idx = tid + r*256;                                                 \
            int ar = idx >> 3, ac = (idx & 7) * 8;                                 \
            CPA16(sA + (uint32_t)(bb)*9216u + (uint32_t)ar*144u + (uint32_t)ac*2u, \
                  A + (size_t)(row0+ar)*W3 + (kc) + ac);                           \
        }                                                                          \
        _Pragma("unroll")                                                          \
        for (int r = 0; r < 2; r++) {                                              \
            int idx = tid + r*256;                                                 \
            int br = idx >> 3, bc = (idx & 7) * 8;                                 \
            CPA16(sB + (uint32_t)(bb)*9216u + (uint32_t)br*144u + (uint32_t)bc*2u, \
                  B + (size_t)((kc)+br)*DD + col0 + bc);                           \
        }                                                                          \
        CPA_COMMIT(); }

    WV_STAGE(0, 0);
    for (int s = 0; s < 4; s++) {
        CPA_WAIT(0);
        __syncthreads();
        if (s < 3) WV_STAGE((s+1)*64, (s+1)&1);
        int bb = s & 1;
        #pragma unroll
        for (int k4 = 0; k4 < 4; k4++) {
            wmma::fragment<wmma::matrix_a,16,16,16,__nv_bfloat16,wmma::row_major> af[2];
            wmma::fragment<wmma::matrix_b,16,16,16,__nv_bfloat16,wmma::row_major> bf;
            #pragma unroll
            for (int i = 0; i < 2; i++)
                wmma::load_matrix_sync(af[i], &As[bb][wm*32 + i*16][k4*16], 72);
            wmma::load_matrix_sync(bf, &Bs[bb][k4*16][wn*16], 72);
            #pragma unroll
            for (int i = 0; i < 2; i++)
                wmma::mma_sync(acc[i], af[i], bf, acc[i]);
        }
    }
    #undef WV_STAGE
    __syncthreads();

    int r = lane >> 1, c8 = (lane & 1) * 8;
    #pragma unroll
    for (int i = 0; i < 2; i++) {
        wmma::store_matrix_sync(&epi[w][0][0], acc[i], 16, wmma::mem_row_major);
        __syncwarp();
        int gr = row0 + wm*32 + i*16 + r;
        int gc = col0 + wn*16 + c8;
        __nv_bfloat16 t8[8];
        #pragma unroll
        for (int e = 0; e < 8; e++)
            t8[e] = __float2bfloat16(epi[w][r][c8+e]);
        *(uint4*)(g_Wvf2b + (size_t)gr*DD + gc) = *(uint4*)t8;
        __syncwarp();
    }
}

// ===== prep1: proj_agents || Wvf2 || dbias || bvf2 (grid 89, 256 thr) ========
__global__ void __launch_bounds__(256) prep1(const float* __restrict__ bqkv,
                                             const float* __restrict__ Wfc1,
                                             const float* __restrict__ bfc1,
                                             const float* __restrict__ Wfc2) {
    extern __shared__ __align__(16) char sm[];
    int bid = blockIdx.x;
    if (bid < 8) {
        dev_proj_agents(sm, bid & 3, bid >> 2);
    } else if (bid < 24) {
        int t = bid - 8;
        dev_wvf2(sm, t & 3, t >> 2);
    } else if (bid < 88) {
        float* red = (float*)sm;
        int a = bid - 24, i = threadIdx.x;
        red[i] = bqkv[i] * g_kaf[a*DD + i];
        __syncthreads();
        for (int st = 128; st > 0; st >>= 1) {
            if (i < st) red[i] += red[i + st];
            __syncthreads();
        }
        if (i == 0) g_dbias[a] = red[0];
    } else {
        // bvf2 = (bv@Wfc1 + bfc1) @ Wfc2, two chained GEMVs
        float* bvf = (float*)sm;
        int j = threadIdx.x;
        float t = bfc1[j];
        #pragma unroll 8
        for (int o = 0; o < DD; o++)
            t += bqkv[2*DD + o] * Wfc1[o*DD + j];
        bvf[j] = t;
        __syncthreads();
        float t2 = 0.f;
        #pragma unroll 8
        for (int o = 0; o < DD; o++)
            t2 += bvf[o] * Wfc2[o*DD + j];
        g_bvf2[j] = t2;
    }
}

// ======== fused stage-1 (SPL=32, X-resident, fp32 src): logits->softmax->u ===
// smem: X[128][264]@0 (67584) | Qa 2x[64][40]@67584 (10240) | L[64][136]@77824 (17408)
//       epi[8][16][16]@95232 (8192). total 103424
__global__ void __launch_bounds__(256, 2) s1fused(const float* __restrict__ x) {
    extern __shared__ __align__(16) char smf[];
    __nv_bfloat16 (*X)[264]     = ( __nv_bfloat16(*)[264]) smf;
    __nv_bfloat16 (*Qa)[64][40] = ( __nv_bfloat16(*)[64][40]) (smf + 67584);
    __nv_bfloat16 (*L)[136]     = ( __nv_bfloat16(*)[136])    (smf + 77824);
    float (*epi)[16][16]        = ( float(*)[16][16])         (smf + 95232);
    uint32_t sQ = smem_u32(smf) + 67584u;

    int split = blockIdx.x, b = blockIdx.y;
    int tok0 = split * TSPL;
    int tid = threadIdx.x;
    int w = tid >> 5, lane = tid & 31;
    int wm = w >> 2, wn = w & 3;

    // ---- load + convert X tile [128,256] from fp32 x ----
    {
        const float* xsrc = x + (size_t)(b*NT + tok0)*DD;
        #pragma unroll
        for (int r = 0; r < 16; r++) {
            int idx = tid + r*256;
            int xr = idx >> 5, xc = (idx & 31) * 8;
            float4 v0 = *(const float4*)(xsrc + (size_t)xr*DD + xc);
            float4 v1 = *(const float4*)(xsrc + (size_t)xr*DD + xc + 4);
            __nv_bfloat16 t8[8];
            cvt8(t8, v0, v1);
            *(uint4*)(&X[xr][xc]) = *(uint4*)t8;
        }
    }

    // ---- pass 1: logits[64,128] = qa' @ X^T; Qa staged via cp.async ----
    #define F1_STAGE(kc, bb) {                                                     \
        int ar = tid >> 2, ac = (tid & 3) * 8;                                     \
        CPA16(sQ + (uint32_t)(bb)*5120u + (uint32_t)ar*80u + (uint32_t)ac*2u,      \
              g_qap + (size_t)ar*DD + (kc) + ac);                                  \
        CPA_COMMIT(); }

    {
        wmma::fragment<wmma::accumulator,16,16,16,float> acc[2][2];
        #pragma unroll
        for (int i = 0; i < 2; i++)
            #pragma unroll
            for (int j = 0; j < 2; j++) wmma::fill_fragment(acc[i][j], 0.f);

        F1_STAGE(0, 0);
        for (int s = 0; s < 8; s++) {
            CPA_WAIT(0);
            __syncthreads();
            if (s < 7) F1_STAGE((s+1)*32, (s+1)&1);
            int bb = s & 1;
            #pragma unroll
            for (int kk = 0; kk < 2; kk++) {
                wmma::fragment<wmma::matrix_a,16,16,16,__nv_bfloat16,wmma::row_major> af[2];
                wmma::fragment<wmma::matrix_b,16,16,16,__nv_bfloat16,wmma::col_major> bf[2];
                #pragma unroll
                for (int i = 0; i < 2; i++)
                    wmma::load_matrix_sync(af[i], &Qa[bb][wm*32 + i*16][kk*16], 40);
                #pragma unroll
                for (int j = 0; j < 2; j++)
                    wmma::load_matrix_sync(bf[j], &X[wn*32 + j*16][s*32 + kk*16], 264);
                #pragma unroll
                for (int i = 0; i < 2; i++)
                    #pragma unroll
                    for (int j = 0; j < 2; j++)
                        wmma::mma_sync(acc[i][j], af[i], bf[j], acc[i][j]);
            }
        }
        __syncthreads();
        #pragma unroll
        for (int i = 0; i < 2; i++)
            #pragma unroll
            for (int j = 0; j < 2; j++) {
                wmma::store_matrix_sync(&epi[w][0][0], acc[i][j], 16, wmma::mem_row_major);
                __syncwarp();
                if (lane < 16) {
                    int ga = wm*32 + i*16 + lane;
                    int gc = wn*32 + j*16;
                    __nv_bfloat16 t8[8];
                    #pragma unroll
                    for (int g = 0; g < 2; g++) {
                        #pragma unroll
                        for (int e = 0; e < 8; e++)
                            t8[e] = __float2bfloat16(epi[w][lane][g*8+e]);
                        *(uint4*)(&L[ga][gc + g*8]) = *(uint4*)t8;
                    }
                }
                __syncwarp();
            }
        __syncthreads();
    }
    #undef F1_STAGE

    // ---- split softmax over 128 cols: row = tid>>2, 4 threads/row ----
    {
        int row = tid >> 2, q = tid & 3;
        float m = -1e30f;
        #pragma unroll 8
        for (int c = 0; c < 32; c++)
            m = fmaxf(m, __bfloat162float(L[row][q*32 + c]));
        m = fmaxf(m, __shfl_xor_sync(0xffffffffu, m, 1));
        m = fmaxf(m, __shfl_xor_sync(0xffffffffu, m, 2));
        float sum = 0.f;
        #pragma unroll 8
        for (int c = 0; c < 32; c++) {
            float p = __expf(__bfloat162float(L[row][q*32 + c]) - m);
            sum += p;
            L[row][q*32 + c] = __float2bfloat16(p);
        }
        sum += __shfl_xor_sync(0xffffffffu, sum, 1);
        sum += __shfl_xor_sync(0xffffffffu, sum, 2);
        if (q == 0)
            g_stats[(b*SPL + split)*NA + row] = make_float2(m, sum);
    }
    __syncthreads();

    // ---- pass 2: u_split[64,256] = P[64,128] @ X[128,256]; no staging ----
    {
        wmma::fragment<wmma::accumulator,16,16,16,float> acc[2][4];
        #pragma unroll
        for (int i = 0; i < 2; i++)
            #pragma unroll
            for (int j = 0; j < 4; j++) wmma::fill_fragment(acc[i][j], 0.f);

        #pragma unroll
        for (int kk = 0; kk < 8; kk++) {
            wmma::fragment<wmma::matrix_a,16,16,16,__nv_bfloat16,wmma::row_major> af[2];
            wmma::fragment<wmma::matrix_b,16,16,16,__nv_bfloat16,wmma::row_major> bf[4];
            #pragma unroll
            for (int i = 0; i < 2; i++)
                wmma::load_matrix_sync(af[i], &L[wm*32 + i*16][kk*16], 136);
            #pragma unroll
            for (int j = 0; j < 4; j++)
                wmma::load_matrix_sync(bf[j], &X[kk*16][wn*64 + j*16], 264);
            #pragma unroll
            for (int i = 0; i < 2; i++)
                #pragma unroll
                for (int j = 0; j < 4; j++)
                    wmma::mma_sync(acc[i][j], af[i], bf[j], acc[i][j]);
        }
        __syncthreads();

        __nv_bfloat16* outb = g_vapb + (size_t)(b*SPL + split)*NA*DD;
        #pragma unroll
        for (int i = 0; i < 2; i++)
            #pragma unroll
            for (int j = 0; j < 4; j++) {
                wmma::store_matrix_sync(&epi[w][0][0], acc[i][j], 16, wmma::mem_row_major);
                __syncwarp();
                #pragma unroll
                for (int e = 0; e < 2; e++) {
                    int idx2 = lane + e*32;
                    int r = idx2 >> 2, c4 = (idx2 & 3) * 4;
                    int ga = wm*32 + i*16 + r;
                    int gd = wn*64 + j*16 + c4;
                    __nv_bfloat16 t4[4];
                    #pragma unroll
                    for (int e2 = 0; e2 < 4; e2++)
                        t4[e2] = __float2bfloat16(epi[w][r][c4+e2]);
                    *(uint2*)(outb + (size_t)ga*DD + gd) = *(uint2*)t4;
                }
                __syncwarp();
            }
    }
}

// ---------------- combine (grid 512 x 128): log-sum-exp merge -> u bf16 ------
__global__ void __launch_bounds__(128) combine_k() {
    __shared__ float ms[SPL], ss[SPL];
    int row = blockIdx.x;
    int b = row >> 6, a = row & 63;
    int tid = threadIdx.x;

    if (tid < SPL) {
        float2 st = g_stats[(b*SPL + tid)*NA + a];
        ms[tid] = st.x; ss[tid] = st.y;
    }
    __syncthreads();

    float m = -1e30f;
    #pragma unroll
    for (int s = 0; s < SPL; s++) m = fmaxf(m, ms[s]);
    float S = 0.f;
    float wsc[SPL];
    #pragma unroll
    for (int s = 0; s < SPL; s++) {
        wsc[s] = __expf(ms[s] - m);
        S += wsc[s] * ss[s];
    }
    float invS = 1.f / S;

    float acc[2] = {0.f, 0.f};
    const __nv_bfloat16* base = g_vapb + (size_t)b*SPL*NA*DD + (size_t)a*DD + tid*2;
    #pragma unroll
    for (int s = 0; s < SPL; s++) {
        __nv_bfloat16 t2[2];
        *(uint32_t*)t2 = *(const uint32_t*)(base + (size_t)s*NA*DD);
        acc[0] += wsc[s] * __bfloat162float(t2[0]);
        acc[1] += wsc[s] * __bfloat162float(t2[1]);
    }
    __nv_bfloat16 o2[2];
    o2[0] = __float2bfloat16(acc[0] * invS);
    o2[1] = __float2bfloat16(acc[1] * invS);
    *(uint32_t*)(g_ub + (size_t)row*DD + tid*2) = *(uint32_t*)o2;
}

// ---------------- fc2v: va2[512,256] = u @ Wvf2b + bvf2 (WMMA) ---------------
__global__ void __launch_bounds__(256) fc2v() {
    __shared__ __nv_bfloat16 As[2][64][72];
    __shared__ __nv_bfloat16 Bs[2][64][72];
    __shared__ float epi[8][16][16];
    uint32_t sA = smem_u32(&As[0][0][0]), sB = smem_u32(&Bs[0][0][0]);

    int row0 = blockIdx.y * 64, col0 = blockIdx.x * 64;
    int tid = threadIdx.x, w = tid >> 5, lane = tid & 31;
    int wm = w >> 2, wn = w & 3;

    wmma::fragment<wmma::accumulator,16,16,16,float> acc[2];
    #pragma unroll
    for (int i = 0; i < 2; i++) wmma::fill_fragment(acc[i], 0.f);

    #define FV_STAGE(kc, bb) {                                                     \
        _Pragma("unroll")                                                          \
        for (int r = 0; r < 2; r++) {                                              \
            int idx = tid + r*256;                                                 \
            int ar = idx >> 3, ac = (idx & 7) * 8;                                 \
            CPA16(sA + (uint32_t)(bb)*9216u + (uint32_t)ar*144u + (uint32_t)ac*2u, \
                  g_ub + (size_t)(row0+ar)*DD + (kc) + ac);                        \
        }                                                                          \
        _Pragma("unroll")                                                          \
        for (int r = 0; r < 2; r++) {                                              \
            int idx = tid + r*256;                                                 \
            int br = idx >> 3, bc = (idx & 7) * 8;                                 \
            CPA16(sB + (uint32_t)(bb)*9216u + (uint32_t)br*144u + (uint32_t)bc*2u, \
                  g_Wvf2b + (size_t)((kc)+br)*DD + col0 + bc);                     \
        }                                                                          \
        CPA_COMMIT(); }

    FV_STAGE(0, 0);
    for (int s = 0; s < 4; s++) {
        CPA_WAIT(0);
        __syncthreads();
        if (s < 3) FV_STAGE((s+1)*64, (s+1)&1);
        int bb = s & 1;
        #pragma unroll
        for (int k4 = 0; k4 < 4; k4++) {
            wmma::fragment<wmma::matrix_a,16,16,16,__nv_bfloat16,wmma::row_major> af[2];
            wmma::fragment<wmma::matrix_b,16,16,16,__nv_bfloat16,wmma::row_major> bf;
            #pragma unroll
            for (int i = 0; i < 2; i++)
                wmma::load_matrix_sync(af[i], &As[bb][wm*32 + i*16][k4*16], 72);
            wmma::load_matrix_sync(bf, &Bs[bb][k4*16][wn*16], 72);
            #pragma unroll
            for (int i = 0; i < 2; i++)
                wmma::mma_sync(acc[i], af[i], bf, acc[i]);
        }
    }
    #undef FV_STAGE
    __syncthreads();

    int r = lane >> 1, c8 = (lane & 1) * 8;
    #pragma unroll
    for (int i = 0; i < 2; i++) {
        wmma::store_matrix_sync(&epi[w][0][0], acc[i], 16, wmma::mem_row_major);
        __syncwarp();
        int gr = row0 + wm*32 + i*16 + r;
        int gc = col0 + wn*16 + c8;
        __nv_bfloat16 t8[8];
        #pragma unroll
        for (int e = 0; e < 8; e++)
            t8[e] = __float2bfloat16(epi[w][r][c8+e] + g_bvf2[gc+e]);
        *(uint4*)(g_va + (size_t)gr*DD + gc) = *(uint4*)t8;
        __syncwarp();
    }
}

// ======== stage 2 (64-token tiles, fp32 x): logits->softmax->P@va2+bfc2+x ====
// smem: Xb[64][264]@0 (33792) | Ka 2x[64][40]@33792 (10240) | logits@44032 (17408)
//       Vs[64][264]@61440 (33792). total 95232. Pm reuses Xb; epi reuses Ka.
__global__ void __launch_bounds__(256) stage2(const float* __restrict__ bfc2,
                                              const float* __restrict__ x,
                                              float* __restrict__ out) {
    extern __shared__ __align__(16) char sm2[];
    __nv_bfloat16 (*Xb)[264]    = ( __nv_bfloat16(*)[264])    sm2;
    __nv_bfloat16 (*Ka)[64][40] = ( __nv_bfloat16(*)[64][40]) (sm2 + 33792);
    float* logits               = ( float*)                   (sm2 + 44032);
    __nv_bfloat16 (*Vs)[264]    = ( __nv_bfloat16(*)[264])    (sm2 + 61440);
    __nv_bfloat16 (*Pm)[72]     = ( __nv_bfloat16(*)[72])     sm2;
    float (*epi)[16][16]        = ( float(*)[16][16])         (sm2 + 33792);
    __shared__ float dbs[NA];
    uint32_t sKa = smem_u32(sm2) + 33792u, sV = smem_u32(sm2) + 61440u;

    int b = blockIdx.y, t0 = blockIdx.x * 64;
    int tid = threadIdx.x;
    int w = tid >> 5, lane = tid & 31;
    int wm = w >> 2, wn = w & 3;

    if (tid < NA) dbs[tid] = g_dbias[tid];

    // async prefetch va2 tile [64,256] into Vs
    #pragma unroll
    for (int r = 0; r < 8; r++) {
        int idx = tid + r*256;
        int vr = idx >> 5, vc = (idx & 31) * 8;
        CPA16(sV + (uint32_t)vr*528u + (uint32_t)vc*2u,
              g_va + (size_t)(b*NA + vr)*DD + vc);
    }
    CPA_COMMIT();

    // ---- load + convert X tile [64,256] from fp32 x ----
    {
        const float* xsrc = x + (size_t)(b*NT + t0)*DD;
        #pragma unroll
        for (int r = 0; r < 8; r++) {
            int idx = tid + r*256;
            int xr = idx >> 5, xc = (idx & 31) * 8;
            float4 v0 = *(const float4*)(xsrc + (size_t)xr*DD + xc);
            float4 v1 = *(const float4*)(xsrc + (size_t)xr*DD + xc + 4);
            __nv_bfloat16 t8[8];
            cvt8(t8, v0, v1);
            *(uint4*)(&Xb[xr][xc]) = *(uint4*)t8;
        }
    }

    // --- phase A: logits[64,64] = Xb[64,256] @ Ka'[64,256]^T; Ka cp.async ---
    {
        wmma::fragment<wmma::accumulator,16,16,16,float> acc[2];
        #pragma unroll
        for (int i = 0; i < 2; i++) wmma::fill_fragment(acc[i], 0.f);

        #define S2_STAGE(kc, bb) {                                                 \
            int ar = tid >> 2, ac = (tid & 3) * 8;                                 \
            CPA16(sKa + (uint32_t)(bb)*5120u + (uint32_t)ar*80u + (uint32_t)ac*2u, \
                  g_kat + (size_t)ar*DD + (kc) + ac);                              \
            CPA_COMMIT(); }

        S2_STAGE(0, 0);
        for (int s = 0; s < 8; s++) {
            CPA_WAIT(0);
            __syncthreads();
            if (s < 7) S2_STAGE((s+1)*32, (s+1)&1);
            int bb = s & 1;
            #pragma unroll
            for (int kk = 0; kk < 2; kk++) {
                wmma::fragment<wmma::matrix_a,16,16,16,__nv_bfloat16,wmma::row_major> af[2];
                wmma::fragment<wmma::matrix_b,16,16,16,__nv_bfloat16,wmma::col_major> bf;
                #pragma unroll
                for (int i = 0; i < 2; i++)
                    wmma::load_matrix_sync(af[i], &Xb[wm*32 + i*16][s*32 + kk*16], 264);
                wmma::load_matrix_sync(bf, &Ka[bb][wn*16][kk*16], 40);
                #pragma unroll
                for (int i = 0; i < 2; i++)
                    wmma::mma_sync(acc[i], af[i], bf, acc[i]);
            }
        }
        #undef S2_STAGE
        __syncthreads();
        #pragma unroll
        for (int i = 0; i < 2; i++)
            wmma::store_matrix_sync(logits + (wm*32 + i*16)*68 + wn*16,
                                    acc[i], 68, wmma::mem_row_major);
    }
    __syncthreads();

    // --- phase B: per-row softmax over 64 agents (+dbias); 4 threads/row ---
    {
        int row = tid >> 2, q = tid & 3;
        const float* lr = logits + row*68 + q*16;
        float lv[16];
        #pragma unroll
        for (int c = 0; c < 16; c++) lv[c] = lr[c] + dbs[q*16 + c];
        float m = -1e30f;
        #pragma unroll
        for (int c = 0; c < 16; c++) m = fmaxf(m, lv[c]);
        m = fmaxf(m, __shfl_xor_sync(0xffffffffu, m, 1));
        m = fmaxf(m, __shfl_xor_sync(0xffffffffu, m, 2));
        float sum = 0.f;
        float pv[16];
        #pragma unroll
        for (int c = 0; c < 16; c++) { pv[c] = __expf(lv[c] - m); sum += pv[c]; }
        sum += __shfl_xor_sync(0xffffffffu, sum, 1);
        sum += __shfl_xor_sync(0xffffffffu, sum, 2);
        float inv = 1.f / sum;
        __syncthreads();   // Xb reads (phase A) done before Pm overwrite
        #pragma unroll
        for (int c = 0; c < 16; c++)
            Pm[row][q*16 + c] = __float2bfloat16(pv[c] * inv);
    }
    __syncthreads();

    // --- phase C: out[64,256] = Pm[64,64] @ Vs[64,256] + bfc2 + x ---
    {
        wmma::fragment<wmma::accumulator,16,16,16,float> acc[2][4];
        #pragma unroll
        for (int i = 0; i < 2; i++)
            #pragma unroll
            for (int j = 0; j < 4; j++) wmma::fill_fragment(acc[i][j], 0.f);
        #pragma unroll
        for (int kk = 0; kk < 4; kk++) {
            wmma::fragment<wmma::matrix_a,16,16,16,__nv_bfloat16,wmma::row_major> af[2];
            wmma::fragment<wmma::matrix_b,16,16,16,__nv_bfloat16,wmma::row_major> bf[4];
            #pragma unroll
            for (int i = 0; i < 2; i++)
                wmma::load_matrix_sync(af[i], &Pm[wm*32 + i*16][kk*16], 72);
            #pragma unroll
            for (int j = 0; j < 4; j++)
                wmma::load_matrix_sync(bf[j], &Vs[kk*16][wn*64 + j*16], 264);
            #pragma unroll
            for (int i = 0; i < 2; i++)
                #pragma unroll
                for (int j = 0; j < 4; j++)
                    wmma::mma_sync(acc[i][j], af[i], bf[j], acc[i][j]);
        }
        __syncthreads();
        int r = lane >> 1, c8 = (lane & 1) * 8;
        #pragma unroll
        for (int i = 0; i < 2; i++)
            #pragma unroll
            for (int j = 0; j < 4; j++) {
                wmma::store_matrix_sync(&epi[w][0][0], acc[i][j], 16, wmma::mem_row_major);
                __syncwarp();
                int grow = t0 + wm*32 + i*16 + r;
                int gcol = wn*64 + j*16 + c8;
                size_t gi = (size_t)(b*NT + grow)*DD + gcol;
                float o0[4], o1[4];
                #pragma unroll
                for (int e = 0; e < 4; e++)
                    o0[e] = epi[w][r][c8+e]   + bfc2[gcol+e]   + x[gi+e];
                #pragma unroll
                for (int e = 0; e < 4; e++)
                    o1[e] = epi[w][r][c8+4+e] + bfc2[gcol+4+e] + x[gi+4+e];
                *(float4*)(out + gi)     = *(float4*)o0;
                *(float4*)(out + gi + 4) = *(float4*)o1;
                __syncwarp();
            }
    }
}

// ---------------- launcher ---------------------------------------------------
#define S1F_SMEM 103424
#define S2_SMEM  95232
#define PREP_SMEM 45056

extern "C" void kernel_launch(void* const* d_in, const int* in_sizes, int n_in,
                              void* d_out, int out_size) {
    const float* agent = (const float*)d_in[0];
    const float* x     = (const float*)d_in[1];
    const float* Wqkv  = (const float*)d_in[2];
    const float* bqkv  = (const float*)d_in[3];
    const float* Wag   = (const float*)d_in[4];
    const float* bag   = (const float*)d_in[5];
    const float* Wfc1  = (const float*)d_in[6];
    const float* bfc1  = (const float*)d_in[7];
    const float* Wfc2  = (const float*)d_in[8];
    const float* bfc2  = (const float*)d_in[9];
    float* out = (float*)d_out;

    cudaFuncSetAttribute(s1fused, cudaFuncAttributeMaxDynamicSharedMemorySize, S1F_SMEM);
    cudaFuncSetAttribute(stage2,  cudaFuncAttributeMaxDynamicSharedMemorySize, S2_SMEM);
    cudaFuncSetAttribute(prep0,   cudaFuncAttributeMaxDynamicSharedMemorySize, PREP_SMEM);

    prep0<<<112, 512, PREP_SMEM>>>(Wqkv, Wfc1, Wfc2, agent, Wag, bag);
    prep1<<<89, 256, PREP_SMEM>>>(bqkv, Wfc1, bfc1, Wfc2);
    s1fused<<<dim3(SPL, NB), 256, S1F_SMEM>>>(x);
    combine_k<<<512, 128>>>();
    fc2v<<<dim3(4, 8), 256>>>();
    stage2<<<dim3(64, 8), 256, S2_SMEM>>>(bfc2, x, out);
}